// round 11
// baseline (speedup 1.0000x reference)
#include <cuda_runtime.h>
#include <cuda_fp16.h>
#include <math.h>

#define H 128
#define E_MAX 80000
#define N_MAX 40000

// ---------------- scratch (device globals; no allocation allowed) ----------
__device__ __align__(16) float g_Pz [E_MAX * H];
__device__ __align__(16) float g_Pr [E_MAX * H];
__device__ __align__(16) float g_Ph [E_MAX * H];
__device__ __align__(16) float g_q1 [E_MAX * H];
__device__ __align__(16) float g_q2 [E_MAX * H];
__device__ __align__(16) float g_hA [E_MAX * H];
__device__ __align__(16) float g_hB [E_MAX * H];
__device__ int g_bg32[E_MAX * 6];
__device__ int g_ag32[N_MAX * 6];
__device__ int g_idx_is64;

__device__ __forceinline__ float sigmoidf_(float x) { return 1.0f / (1.0f + expf(-x)); }
__device__ __forceinline__ unsigned pk(float a, float b) {
    __half2 h = __floats2half2_rn(a, b);
    return *reinterpret_cast<unsigned*>(&h);
}

#define MMA_F16(C, A0,A1,A2,A3, B0,B1) \
    asm volatile("mma.sync.aligned.m16n8k16.row.col.f32.f16.f16.f32 " \
        "{%0,%1,%2,%3},{%4,%5,%6,%7},{%8,%9},{%0,%1,%2,%3};" \
        : "+f"((C)[0]), "+f"((C)[1]), "+f"((C)[2]), "+f"((C)[3]) \
        : "r"(A0), "r"(A1), "r"(A2), "r"(A3), "r"(B0), "r"(B1))

#define LDSM_X4(R0,R1,R2,R3,ADDR) \
    asm volatile("ldmatrix.sync.aligned.m8n8.x4.shared.b16 {%0,%1,%2,%3}, [%4];" \
        : "=r"(R0), "=r"(R1), "=r"(R2), "=r"(R3) : "r"(ADDR))

#define LDSM_X4_T(R0,R1,R2,R3,ADDR) \
    asm volatile("ldmatrix.sync.aligned.m8n8.x4.trans.shared.b16 {%0,%1,%2,%3}, [%4];" \
        : "=r"(R0), "=r"(R1), "=r"(R2), "=r"(R3) : "r"(ADDR))

// ---------------------------------------------------------------------------
// Index dtype normalize (JAX may ship int32 despite int64 in source).
// ---------------------------------------------------------------------------
__global__ void detect_idx_kernel(const unsigned int* __restrict__ w)
{
    g_idx_is64 = (w[1] == 0u && w[3] == 0u && w[5] == 0u && w[7] == 0u) ? 1 : 0;
}
__global__ void convert_idx_kernel(const void* __restrict__ src, int* __restrict__ dst, int n)
{
    int i = blockIdx.x * blockDim.x + threadIdx.x;
    if (i >= n) return;
    if (g_idx_is64) dst[i] = (int)((const long long*)src)[i];
    else            dst[i] = ((const int*)src)[i];
}

// ---------------------------------------------------------------------------
// fp16 GEMM helper: A resident in smem as halves [rows][136] (stride 272B),
// C += A[.., 0:128] @ W[0:128, 0:128].  Wb = [16][136] halves staging.
// Warp tile = 32 x (NT*8).  Fragments via ldmatrix (conflict-free strides).
// ---------------------------------------------------------------------------
template<int NT>
__device__ __forceinline__ void gemm_smemA_f16(
    unsigned AsB,                       // u32 smem addr of As[0][0]
    const float* __restrict__ W,        // gmem [128][128] fp32
    __half (*Wb)[136], unsigned WbB,
    float (&C)[2][NT][4],
    int wr, int wc, int lane, int tid)
{
    const int aRowOff = (wr + (lane & 15)) * 272 + ((lane >> 4) * 8) * 2;
    const int bAddr0  = ((lane & 7) + ((lane >> 3) & 1) * 8) * 272
                      + (wc + (lane >> 4) * 8) * 2;
    const int wrow = tid >> 4, wcb = (tid & 15) * 8;

    for (int k0 = 0; k0 < 128; k0 += 16) {
        // stage W chunk [16 x 128] fp32 -> half
        {
            const float* p = W + (size_t)(k0 + wrow) * H + wcb;
            const float4 v0 = *(const float4*)p, v1 = *(const float4*)(p + 4);
            uint4 w;
            w.x = pk(v0.x, v0.y); w.y = pk(v0.z, v0.w);
            w.z = pk(v1.x, v1.y); w.w = pk(v1.z, v1.w);
            *(uint4*)&Wb[wrow][wcb] = w;
        }
        __syncthreads();

        unsigned a[2][4];
#pragma unroll
        for (int mi = 0; mi < 2; ++mi)
            LDSM_X4(a[mi][0], a[mi][1], a[mi][2], a[mi][3],
                    AsB + aRowOff + mi * 16 * 272 + k0 * 2);
#pragma unroll
        for (int pr = 0; pr < NT / 2; ++pr) {
            unsigned b0, b1, b2, b3;
            LDSM_X4_T(b0, b1, b2, b3, WbB + bAddr0 + pr * 32);
            MMA_F16(C[0][2*pr],   a[0][0], a[0][1], a[0][2], a[0][3], b0, b1);
            MMA_F16(C[0][2*pr+1], a[0][0], a[0][1], a[0][2], a[0][3], b2, b3);
            MMA_F16(C[1][2*pr],   a[1][0], a[1][1], a[1][2], a[1][3], b0, b1);
            MMA_F16(C[1][2*pr+1], a[1][0], a[1][1], a[1][2], a[1][3], b2, b3);
        }
        __syncthreads();
    }
}

// ---------------------------------------------------------------------------
// mm3: out[w] = X @ W[w] + bias[w]   (fp16 MMA, BM=128, double-buffered)
// Grid = (3, rowTiles): blockIdx.x = weight set (fastest dim) so the three
// blocks reading the same X tile are schedule-adjacent -> X hits L2 twice.
// ---------------------------------------------------------------------------
__global__ void __launch_bounds__(256)
mm3_kernel(const float* __restrict__ X, int ldx, int M, int K,
           const float* __restrict__ W0, const float* __restrict__ W1, const float* __restrict__ W2,
           const float* __restrict__ b0, const float* __restrict__ b1, const float* __restrict__ b2,
           float* __restrict__ o0, float* __restrict__ o1, float* __restrict__ o2)
{
    __shared__ __align__(16) __half Xs[2][128][24];   // stride 48B, conflict-free ldsm
    __shared__ __align__(16) __half Ws[2][16][136];   // stride 272B

    const float* W   = (blockIdx.x == 0) ? W0 : (blockIdx.x == 1) ? W1 : W2;
    const float* bia = (blockIdx.x == 0) ? b0 : (blockIdx.x == 1) ? b1 : b2;
    float*       out = (blockIdx.x == 0) ? o0 : (blockIdx.x == 1) ? o1 : o2;

    const int tid = threadIdx.x, warp = tid >> 5, lane = tid & 31;
    const int gid = lane >> 2, tig = lane & 3;
    const int wr = (warp >> 1) * 32, wc = (warp & 1) * 64;
    const int brow = blockIdx.y * 128;

    const int xrow = tid >> 1, xcb = (tid & 1) * 8;
    const int wrow = tid >> 4, wcb = (tid & 15) * 8;
    const int xgr  = brow + xrow;

    const unsigned xs0 = (unsigned)__cvta_generic_to_shared(&Xs[0][0][0]);
    const unsigned ws0 = (unsigned)__cvta_generic_to_shared(&Ws[0][0][0]);
    const int aRowOff = (wr + (lane & 15)) * 48 + ((lane >> 4) * 8) * 2;
    const int bAddr0  = ((lane & 7) + ((lane >> 3) & 1) * 8) * 272
                      + (wc + (lane >> 4) * 8) * 2;

    float C[2][8][4];
#pragma unroll
    for (int i = 0; i < 2; ++i)
#pragma unroll
        for (int j = 0; j < 8; ++j)
#pragma unroll
            for (int k = 0; k < 4; ++k) C[i][j][k] = 0.f;

    float4 xv0, xv1, wv0, wv1;

    // prefetch chunk 0
    xv0 = make_float4(0.f,0.f,0.f,0.f); xv1 = xv0;
    if (xgr < M) {
        const float* p = X + (size_t)xgr * ldx + xcb;
        xv0 = *(const float4*)p; xv1 = *(const float4*)(p + 4);
    }
    {
        const float* wp = W + (size_t)wrow * H + wcb;
        wv0 = *(const float4*)wp; wv1 = *(const float4*)(wp + 4);
    }
    {
        uint4 xw; xw.x = pk(xv0.x,xv0.y); xw.y = pk(xv0.z,xv0.w);
                  xw.z = pk(xv1.x,xv1.y); xw.w = pk(xv1.z,xv1.w);
        *(uint4*)&Xs[0][xrow][xcb] = xw;
        uint4 ww; ww.x = pk(wv0.x,wv0.y); ww.y = pk(wv0.z,wv0.w);
                  ww.z = pk(wv1.x,wv1.y); ww.w = pk(wv1.z,wv1.w);
        *(uint4*)&Ws[0][wrow][wcb] = ww;
    }
    __syncthreads();

    const int nk = K >> 4;
    for (int it = 0; it < nk; ++it) {
        const int buf = it & 1;
        // LDG next chunk (latency hidden under compute)
        if (it + 1 < nk) {
            const int k0 = (it + 1) << 4;
            xv0 = make_float4(0.f,0.f,0.f,0.f); xv1 = xv0;
            if (xgr < M) {
                const float* p = X + (size_t)xgr * ldx + k0 + xcb;
                xv0 = *(const float4*)p; xv1 = *(const float4*)(p + 4);
            }
            const float* wp = W + (size_t)(k0 + wrow) * H + wcb;
            wv0 = *(const float4*)wp; wv1 = *(const float4*)(wp + 4);
        }
        // compute on buf
        {
            const unsigned xb = xs0 + buf * 6144;
            const unsigned wb = ws0 + buf * 4352;
            unsigned a[2][4];
#pragma unroll
            for (int mi = 0; mi < 2; ++mi)
                LDSM_X4(a[mi][0], a[mi][1], a[mi][2], a[mi][3],
                        xb + aRowOff + mi * 16 * 48);
#pragma unroll
            for (int pr = 0; pr < 4; ++pr) {
                unsigned bb0, bb1, bb2, bb3;
                LDSM_X4_T(bb0, bb1, bb2, bb3, wb + bAddr0 + pr * 32);
                MMA_F16(C[0][2*pr],   a[0][0], a[0][1], a[0][2], a[0][3], bb0, bb1);
                MMA_F16(C[0][2*pr+1], a[0][0], a[0][1], a[0][2], a[0][3], bb2, bb3);
                MMA_F16(C[1][2*pr],   a[1][0], a[1][1], a[1][2], a[1][3], bb0, bb1);
                MMA_F16(C[1][2*pr+1], a[1][0], a[1][1], a[1][2], a[1][3], bb2, bb3);
            }
        }
        // STS next chunk into other buffer
        if (it + 1 < nk) {
            const int nb = buf ^ 1;
            uint4 xw; xw.x = pk(xv0.x,xv0.y); xw.y = pk(xv0.z,xv0.w);
                      xw.z = pk(xv1.x,xv1.y); xw.w = pk(xv1.z,xv1.w);
            *(uint4*)&Xs[nb][xrow][xcb] = xw;
            uint4 ww; ww.x = pk(wv0.x,wv0.y); ww.y = pk(wv0.z,wv0.w);
                      ww.z = pk(wv1.x,wv1.y); ww.w = pk(wv1.z,wv1.w);
            *(uint4*)&Ws[nb][wrow][wcb] = ww;
        }
        __syncthreads();
    }

#pragma unroll
    for (int mi = 0; mi < 2; ++mi)
#pragma unroll
        for (int ni = 0; ni < 8; ++ni) {
            const int col = wc + ni * 8 + 2 * tig;
            const float bx = bia ? bia[col] : 0.f;
            const float by = bia ? bia[col + 1] : 0.f;
            const int r0 = brow + wr + mi * 16 + gid;
            const int r1 = r0 + 8;
            if (r0 < M) *(float2*)&out[(size_t)r0 * H + col] =
                make_float2(C[mi][ni][0] + bx, C[mi][ni][1] + by);
            if (r1 < M) *(float2*)&out[(size_t)r1 * H + col] =
                make_float2(C[mi][ni][2] + bx, C[mi][ni][3] + by);
        }
}

// ---------------------------------------------------------------------------
// fused_iter1: h = sigmoid(Pz)*tanh(Ph) -> global + smem(half); q = h @ Ur.
// BM=64, warps 2x4 (warp tile 32x32, NT=4).
// ---------------------------------------------------------------------------
__global__ void __launch_bounds__(256)
fused_iter1_kernel(const float* __restrict__ Pz, const float* __restrict__ Ph,
                   const float* __restrict__ Ur,
                   float* __restrict__ h_out, float* __restrict__ q_out, int E)
{
    __shared__ __align__(16) __half As[64][136];
    __shared__ __align__(16) __half Wb[16][136];

    const int tid = threadIdx.x, lane = tid & 31, ty = tid >> 5;
    const int gid = lane >> 2, tig = lane & 3;
    const int wr = (ty >> 2) * 32, wc = (ty & 3) * 32;
    const int brow = blockIdx.x * 64;
    const int c4 = lane * 4;

    const unsigned AsB = (unsigned)__cvta_generic_to_shared(&As[0][0]);
    const unsigned WbB = (unsigned)__cvta_generic_to_shared(&Wb[0][0]);

#pragma unroll
    for (int pass = 0; pass < 8; ++pass) {
        const int er = pass * 8 + ty;
        const int e  = brow + er;
        float4 v = make_float4(0.f,0.f,0.f,0.f);
        if (e < E) {
            const float4 pz = *(const float4*)&Pz[(size_t)e*H + c4];
            const float4 ph = *(const float4*)&Ph[(size_t)e*H + c4];
            v.x = sigmoidf_(pz.x) * tanhf(ph.x);
            v.y = sigmoidf_(pz.y) * tanhf(ph.y);
            v.z = sigmoidf_(pz.z) * tanhf(ph.z);
            v.w = sigmoidf_(pz.w) * tanhf(ph.w);
            if (e == 0) v = make_float4(0.f,0.f,0.f,0.f);
            *(float4*)&h_out[(size_t)e*H + c4] = v;
        }
        uint2 hv; hv.x = pk(v.x, v.y); hv.y = pk(v.z, v.w);
        *(uint2*)&As[er][c4] = hv;
    }
    __syncthreads();

    float C[2][4][4];
#pragma unroll
    for (int i = 0; i < 2; ++i)
#pragma unroll
        for (int j = 0; j < 4; ++j)
#pragma unroll
            for (int k = 0; k < 4; ++k) C[i][j][k] = 0.f;
    gemm_smemA_f16<4>(AsB, Ur, Wb, WbB, C, wr, wc, lane, tid);

#pragma unroll
    for (int mi = 0; mi < 2; ++mi)
#pragma unroll
        for (int ni = 0; ni < 4; ++ni) {
            const int col = wc + ni * 8 + 2 * tig;
            const int r0 = brow + wr + mi * 16 + gid;
            const int r1 = r0 + 8;
            if (r0 < E) *(float2*)&q_out[(size_t)r0 * H + col] =
                make_float2(C[mi][ni][0], C[mi][ni][1]);
            if (r1 < E) *(float2*)&q_out[(size_t)r1 * H + col] =
                make_float2(C[mi][ni][2], C[mi][ni][3]);
        }
}

// ---------------------------------------------------------------------------
// fused_gru: BM=64, warps 2x4 (warp tile 32x32, NT=4), static smem ~39KB.
// gather(sh,sg) -> smem(half); Cz=sh@Wz2, Ch=sg@Wh2; GRU epilogue -> h_out +
// smem(half); optional q_out = h_new @ Ur.
// ---------------------------------------------------------------------------
__global__ void __launch_bounds__(256)
fused_gru_kernel(const float* __restrict__ h_in, const float* __restrict__ q_in,
                 const int* __restrict__ bg,
                 const float* __restrict__ Pr, const float* __restrict__ Pz,
                 const float* __restrict__ Ph,
                 const float* __restrict__ Wz2, const float* __restrict__ Wh2,
                 const float* __restrict__ Ur,
                 float* __restrict__ h_out, float* __restrict__ q_out,
                 int E, int do_q)
{
    __shared__ __align__(16) __half SHs[64][136];
    __shared__ __align__(16) __half SGs[64][136];
    __shared__ __align__(16) __half Wb[16][136];

    const int tid = threadIdx.x, lane = tid & 31, ty = tid >> 5;
    const int gid = lane >> 2, tig = lane & 3;
    const int wr = (ty >> 2) * 32, wc = (ty & 3) * 32;
    const int brow = blockIdx.x * 64;
    const int c4 = lane * 4;

    const unsigned SHB = (unsigned)__cvta_generic_to_shared(&SHs[0][0]);
    const unsigned SGB = (unsigned)__cvta_generic_to_shared(&SGs[0][0]);
    const unsigned WbB = (unsigned)__cvta_generic_to_shared(&Wb[0][0]);

    // gather phase: 64 edges, 6 neighbors each
#pragma unroll
    for (int pass = 0; pass < 8; ++pass) {
        const int er = pass * 8 + ty;
        const int e  = brow + er;
        float4 sh = make_float4(0.f,0.f,0.f,0.f);
        float4 sg = make_float4(0.f,0.f,0.f,0.f);
        if (e < E) {
            const float4 pr = *(const float4*)&Pr[(size_t)e*H + c4];
#pragma unroll
            for (int j = 0; j < 6; ++j) {
                const int idx = __ldg(&bg[e * 6 + j]);
                const float4 hn = *(const float4*)&h_in[(size_t)idx*H + c4];
                const float4 qn = *(const float4*)&q_in[(size_t)idx*H + c4];
                sh.x += hn.x; sh.y += hn.y; sh.z += hn.z; sh.w += hn.w;
                sg.x += hn.x * sigmoidf_(pr.x + qn.x);
                sg.y += hn.y * sigmoidf_(pr.y + qn.y);
                sg.z += hn.z * sigmoidf_(pr.z + qn.z);
                sg.w += hn.w * sigmoidf_(pr.w + qn.w);
            }
        }
        uint2 a; a.x = pk(sh.x, sh.y); a.y = pk(sh.z, sh.w);
        *(uint2*)&SHs[er][c4] = a;
        uint2 b; b.x = pk(sg.x, sg.y); b.y = pk(sg.z, sg.w);
        *(uint2*)&SGs[er][c4] = b;
    }

    float Cz[2][4][4], Ch[2][4][4];
#pragma unroll
    for (int i = 0; i < 2; ++i)
#pragma unroll
        for (int j = 0; j < 4; ++j)
#pragma unroll
            for (int k = 0; k < 4; ++k) { Cz[i][j][k] = 0.f; Ch[i][j][k] = 0.f; }

    gemm_smemA_f16<4>(SHB, Wz2, Wb, WbB, Cz, wr, wc, lane, tid);
    gemm_smemA_f16<4>(SGB, Wh2, Wb, WbB, Ch, wr, wc, lane, tid);

    // GRU epilogue; write h_out, refill SHs with half(h_new) for q-GEMM
#pragma unroll
    for (int mi = 0; mi < 2; ++mi)
#pragma unroll
        for (int ni = 0; ni < 4; ++ni) {
            const int col = wc + ni * 8 + 2 * tig;
#pragma unroll
            for (int half = 0; half < 2; ++half) {
                const int lr  = wr + mi * 16 + gid + half * 8;
                const int row = brow + lr;
                if (row >= E) continue;
                const size_t base = (size_t)row * H + col;
                const float2 pz = *(const float2*)&Pz[base];
                const float2 ph = *(const float2*)&Ph[base];
                const float sh0 = __half2float(SHs[lr][col]);
                const float sh1 = __half2float(SHs[lr][col + 1]);
                const float z0 = sigmoidf_(Cz[mi][ni][half*2+0] + pz.x);
                const float z1 = sigmoidf_(Cz[mi][ni][half*2+1] + pz.y);
                const float p0 = tanhf(Ch[mi][ni][half*2+0] + ph.x);
                const float p1 = tanhf(Ch[mi][ni][half*2+1] + ph.y);
                float o0 = (1.f - z0) * sh0 + z0 * p0;
                float o1 = (1.f - z1) * sh1 + z1 * p1;
                if (row == 0) { o0 = 0.f; o1 = 0.f; }
                *(float2*)&h_out[base] = make_float2(o0, o1);
                *(unsigned*)&SHs[lr][col] = pk(o0, o1);
            }
        }
    if (!do_q) return;
    __syncthreads();

    float Cq[2][4][4];
#pragma unroll
    for (int i = 0; i < 2; ++i)
#pragma unroll
        for (int j = 0; j < 4; ++j)
#pragma unroll
            for (int k = 0; k < 4; ++k) Cq[i][j][k] = 0.f;
    gemm_smemA_f16<4>(SHB, Ur, Wb, WbB, Cq, wr, wc, lane, tid);

#pragma unroll
    for (int mi = 0; mi < 2; ++mi)
#pragma unroll
        for (int ni = 0; ni < 4; ++ni) {
            const int col = wc + ni * 8 + 2 * tig;
            const int r0 = brow + wr + mi * 16 + gid;
            const int r1 = r0 + 8;
            if (r0 < E) *(float2*)&q_out[(size_t)r0 * H + col] =
                make_float2(Cq[mi][ni][0], Cq[mi][ni][1]);
            if (r1 < E) *(float2*)&q_out[(size_t)r1 * H + col] =
                make_float2(Cq[mi][ni][2], Cq[mi][ni][3]);
        }
}

// ---------------------------------------------------------------------------
// fused_node: BM=64, warps 2x4 (NT=4).
// C = fnode @ Wo[0:256] + gather(nei) @ Wo[256:384]; relu(+bo), row0 mask.
// ---------------------------------------------------------------------------
__global__ void __launch_bounds__(256)
fused_node_kernel(const float* __restrict__ fnode, const float* __restrict__ Wo,
                  const float* __restrict__ h, const int* __restrict__ ag,
                  const float* __restrict__ bo, float* __restrict__ out, int N)
{
    __shared__ __align__(16) __half As[64][136];
    __shared__ __align__(16) __half Wb[16][136];

    const int tid = threadIdx.x, lane = tid & 31, ty = tid >> 5;
    const int gid = lane >> 2, tig = lane & 3;
    const int wr = (ty >> 2) * 32, wc = (ty & 3) * 32;
    const int brow = blockIdx.x * 64;
    const int c4 = lane * 4;

    const unsigned AsB = (unsigned)__cvta_generic_to_shared(&As[0][0]);
    const unsigned WbB = (unsigned)__cvta_generic_to_shared(&Wb[0][0]);
    const int aRowOff = (wr + (lane & 15)) * 272 + ((lane >> 4) * 8) * 2;
    const int bAddr0  = ((lane & 7) + ((lane >> 3) & 1) * 8) * 272
                      + (wc + (lane >> 4) * 8) * 2;
    const int wrow = tid >> 4, wcb = (tid & 15) * 8;

    float C[2][4][4];
#pragma unroll
    for (int i = 0; i < 2; ++i)
#pragma unroll
        for (int j = 0; j < 4; ++j)
#pragma unroll
            for (int k = 0; k < 4; ++k) C[i][j][k] = 0.f;

    // phase A: fnode @ Wo[0:256], per-chunk staging into As cols [0,16)
    for (int k0 = 0; k0 < 256; k0 += 16) {
        {
            const int row = tid >> 2, cb = (tid & 3) * 4;
            const int gr  = brow + row;
            float4 v = make_float4(0.f,0.f,0.f,0.f);
            if (gr < N) v = *(const float4*)&fnode[(size_t)gr * 256 + k0 + cb];
            uint2 hv; hv.x = pk(v.x, v.y); hv.y = pk(v.z, v.w);
            *(uint2*)&As[row][cb] = hv;
        }
        {
            const float* p = Wo + (size_t)(k0 + wrow) * H + wcb;
            const float4 v0 = *(const float4*)p, v1 = *(const float4*)(p + 4);
            uint4 w;
            w.x = pk(v0.x, v0.y); w.y = pk(v0.z, v0.w);
            w.z = pk(v1.x, v1.y); w.w = pk(v1.z, v1.w);
            *(uint4*)&Wb[wrow][wcb] = w;
        }
        __syncthreads();
        unsigned a[2][4];
#pragma unroll
        for (int mi = 0; mi < 2; ++mi)
            LDSM_X4(a[mi][0], a[mi][1], a[mi][2], a[mi][3],
                    AsB + aRowOff + mi * 16 * 272);
#pragma unroll
        for (int pr = 0; pr < 2; ++pr) {
            unsigned bb0, bb1, bb2, bb3;
            LDSM_X4_T(bb0, bb1, bb2, bb3, WbB + bAddr0 + pr * 32);
            MMA_F16(C[0][2*pr],   a[0][0], a[0][1], a[0][2], a[0][3], bb0, bb1);
            MMA_F16(C[0][2*pr+1], a[0][0], a[0][1], a[0][2], a[0][3], bb2, bb3);
            MMA_F16(C[1][2*pr],   a[1][0], a[1][1], a[1][2], a[1][3], bb0, bb1);
            MMA_F16(C[1][2*pr+1], a[1][0], a[1][1], a[1][2], a[1][3], bb2, bb3);
        }
        __syncthreads();
    }

    // phase B: gather nei into As (full width, half)
#pragma unroll
    for (int pass = 0; pass < 8; ++pass) {
        const int nr = pass * 8 + ty;
        const int n  = brow + nr;
        float4 s = make_float4(0.f,0.f,0.f,0.f);
        if (n < N) {
#pragma unroll
            for (int j = 0; j < 6; ++j) {
                const int idx = __ldg(&ag[n * 6 + j]);
                const float4 hn = *(const float4*)&h[(size_t)idx*H + c4];
                s.x += hn.x; s.y += hn.y; s.z += hn.z; s.w += hn.w;
            }
        }
        uint2 hv; hv.x = pk(s.x, s.y); hv.y = pk(s.z, s.w);
        *(uint2*)&As[nr][c4] = hv;
    }
    __syncthreads();

    gemm_smemA_f16<4>(AsB, Wo + 256 * H, Wb, WbB, C, wr, wc, lane, tid);

#pragma unroll
    for (int mi = 0; mi < 2; ++mi)
#pragma unroll
        for (int ni = 0; ni < 4; ++ni) {
            const int col = wc + ni * 8 + 2 * tig;
            const float bx = bo[col], by = bo[col + 1];
#pragma unroll
            for (int half = 0; half < 2; ++half) {
                const int row = brow + wr + mi * 16 + gid + half * 8;
                if (row >= N) continue;
                float o0 = fmaxf(C[mi][ni][half*2+0] + bx, 0.f);
                float o1 = fmaxf(C[mi][ni][half*2+1] + by, 0.f);
                if (row == 0) { o0 = 0.f; o1 = 0.f; }
                *(float2*)&out[(size_t)row * H + col] = make_float2(o0, o1);
            }
        }
}

// ---------------------------------------------------------------------------
extern "C" void kernel_launch(void* const* d_in, const int* in_sizes, int n_in,
                              void* d_out, int out_size)
{
    const float* fnode  = (const float*) d_in[0];
    const float* fmess  = (const float*) d_in[1];
    const void*  agraph = d_in[2];
    const void*  bgraph = d_in[3];
    const float* Wz     = (const float*) d_in[4];
    const float* bz     = (const float*) d_in[5];
    const float* Wr     = (const float*) d_in[6];
    const float* Ur     = (const float*) d_in[7];
    const float* bur    = (const float*) d_in[8];
    const float* Wh     = (const float*) d_in[9];
    const float* bh     = (const float*) d_in[10];
    const float* Wo     = (const float*) d_in[11];
    const float* bo     = (const float*) d_in[12];

    const int N = in_sizes[2] / 6;
    const int E = in_sizes[3] / 6;

    float *Pz, *Pr, *Ph, *q1, *q2, *hA, *hB;
    int *bg32, *ag32;
    cudaGetSymbolAddress((void**)&Pz,   g_Pz);
    cudaGetSymbolAddress((void**)&Pr,   g_Pr);
    cudaGetSymbolAddress((void**)&Ph,   g_Ph);
    cudaGetSymbolAddress((void**)&q1,   g_q1);
    cudaGetSymbolAddress((void**)&q2,   g_q2);
    cudaGetSymbolAddress((void**)&hA,   g_hA);
    cudaGetSymbolAddress((void**)&hB,   g_hB);
    cudaGetSymbolAddress((void**)&bg32, g_bg32);
    cudaGetSymbolAddress((void**)&ag32, g_ag32);

    float* out_node = (float*)d_out;
    const long long need = (long long)(N + E) * H;
    const bool out_has_h = ((long long)out_size >= need);
    float* h_final = out_has_h ? ((float*)d_out + (size_t)N * H) : hA;

    detect_idx_kernel<<<1, 1>>>((const unsigned int*)bgraph);
    convert_idx_kernel<<<(E * 6 + 255) / 256, 256>>>(bgraph, bg32, E * 6);
    convert_idx_kernel<<<(N * 6 + 255) / 256, 256>>>(agraph, ag32, N * 6);

    const int gE128 = (E + 127) / 128;
    const int gE64  = (E + 63) / 64;
    const int gN64  = (N + 63) / 64;

    // loop-invariant precompute; weight-set on blockIdx.x for L2 reuse of X
    mm3_kernel<<<dim3(3, gE128), 256>>>(fmess, 384, E, 384,
                                        Wz, Wr, Wh, bz, bur, bh, Pz, Pr, Ph);

    // iteration 1 (h=0): elementwise h + fused q = h@Ur
    fused_iter1_kernel<<<gE64, 256>>>(Pz, Ph, Ur, hA, q1, E);

    // iteration 2: gather + dual GEMM + GRU + fused q
    fused_gru_kernel<<<gE64, 256>>>(hA, q1, bg32, Pr, Pz, Ph,
                                    Wz + 384 * H, Wh + 384 * H, Ur, hB, q2, E, 1);

    // iteration 3: final h (no q needed)
    fused_gru_kernel<<<gE64, 256>>>(hB, q2, bg32, Pr, Pz, Ph,
                                    Wz + 384 * H, Wh + 384 * H, Ur, h_final, q1, E, 0);

    // output head: fused gather + dual-segment GEMM
    fused_node_kernel<<<gN64, 256>>>(fnode, Wo, h_final, ag32, bo, out_node, N);
}

// round 12
// speedup vs baseline: 1.2170x; 1.2170x over previous
#include <cuda_runtime.h>
#include <cuda_fp16.h>
#include <math.h>

#define H 128
#define E_MAX 80000
#define N_MAX 40000

// ---------------- scratch (device globals; no allocation allowed) ----------
__device__ __align__(16) float g_Pz [E_MAX * H];
__device__ __align__(16) float g_Pr [E_MAX * H];
__device__ __align__(16) float g_Ph [E_MAX * H];
__device__ __align__(16) float g_q1 [E_MAX * H];
__device__ __align__(16) float g_q2 [E_MAX * H];
__device__ __align__(16) float g_hA [E_MAX * H];
__device__ __align__(16) float g_hB [E_MAX * H];
__device__ int g_bg32[E_MAX * 6];
__device__ int g_ag32[N_MAX * 6];
__device__ int g_idx_is64;

__device__ __forceinline__ float sigmoidf_(float x) { return 1.0f / (1.0f + expf(-x)); }
__device__ __forceinline__ unsigned pk(float a, float b) {
    __half2 h = __floats2half2_rn(a, b);
    return *reinterpret_cast<unsigned*>(&h);
}

#define MMA_F16(C, A0,A1,A2,A3, B0,B1) \
    asm volatile("mma.sync.aligned.m16n8k16.row.col.f32.f16.f16.f32 " \
        "{%0,%1,%2,%3},{%4,%5,%6,%7},{%8,%9},{%0,%1,%2,%3};" \
        : "+f"((C)[0]), "+f"((C)[1]), "+f"((C)[2]), "+f"((C)[3]) \
        : "r"(A0), "r"(A1), "r"(A2), "r"(A3), "r"(B0), "r"(B1))

#define LDSM_X4(R0,R1,R2,R3,ADDR) \
    asm volatile("ldmatrix.sync.aligned.m8n8.x4.shared.b16 {%0,%1,%2,%3}, [%4];" \
        : "=r"(R0), "=r"(R1), "=r"(R2), "=r"(R3) : "r"(ADDR))

#define LDSM_X4_T(R0,R1,R2,R3,ADDR) \
    asm volatile("ldmatrix.sync.aligned.m8n8.x4.trans.shared.b16 {%0,%1,%2,%3}, [%4];" \
        : "=r"(R0), "=r"(R1), "=r"(R2), "=r"(R3) : "r"(ADDR))

// ---------------------------------------------------------------------------
// Index dtype normalize (JAX may ship int32 despite int64 in source).
// ---------------------------------------------------------------------------
__global__ void detect_idx_kernel(const unsigned int* __restrict__ w)
{
    g_idx_is64 = (w[1] == 0u && w[3] == 0u && w[5] == 0u && w[7] == 0u) ? 1 : 0;
}
__global__ void convert_idx_kernel(const void* __restrict__ src, int* __restrict__ dst, int n)
{
    int i = blockIdx.x * blockDim.x + threadIdx.x;
    if (i >= n) return;
    if (g_idx_is64) dst[i] = (int)((const long long*)src)[i];
    else            dst[i] = ((const int*)src)[i];
}

// ---------------------------------------------------------------------------
// fp16 GEMM helper: A resident in smem as halves [rows][136] (stride 272B),
// C += A[.., 0:128] @ W[0:128, 0:128].  Wb = [16][136] halves staging.
// Warp tile = 32 x (NT*8).  Fragments via ldmatrix (conflict-free strides).
// ---------------------------------------------------------------------------
template<int NT>
__device__ __forceinline__ void gemm_smemA_f16(
    unsigned AsB,                       // u32 smem addr of As[0][0]
    const float* __restrict__ W,        // gmem [128][128] fp32
    __half (*Wb)[136], unsigned WbB,
    float (&C)[2][NT][4],
    int wr, int wc, int lane, int tid)
{
    const int aRowOff = (wr + (lane & 15)) * 272 + ((lane >> 4) * 8) * 2;
    const int bAddr0  = ((lane & 7) + ((lane >> 3) & 1) * 8) * 272
                      + (wc + (lane >> 4) * 8) * 2;
    const int wrow = tid >> 4, wcb = (tid & 15) * 8;

    for (int k0 = 0; k0 < 128; k0 += 16) {
        // stage W chunk [16 x 128] fp32 -> half
        {
            const float* p = W + (size_t)(k0 + wrow) * H + wcb;
            const float4 v0 = *(const float4*)p, v1 = *(const float4*)(p + 4);
            uint4 w;
            w.x = pk(v0.x, v0.y); w.y = pk(v0.z, v0.w);
            w.z = pk(v1.x, v1.y); w.w = pk(v1.z, v1.w);
            *(uint4*)&Wb[wrow][wcb] = w;
        }
        __syncthreads();

        unsigned a[2][4];
#pragma unroll
        for (int mi = 0; mi < 2; ++mi)
            LDSM_X4(a[mi][0], a[mi][1], a[mi][2], a[mi][3],
                    AsB + aRowOff + mi * 16 * 272 + k0 * 2);
#pragma unroll
        for (int pr = 0; pr < NT / 2; ++pr) {
            unsigned b0, b1, b2, b3;
            LDSM_X4_T(b0, b1, b2, b3, WbB + bAddr0 + pr * 32);
            MMA_F16(C[0][2*pr],   a[0][0], a[0][1], a[0][2], a[0][3], b0, b1);
            MMA_F16(C[0][2*pr+1], a[0][0], a[0][1], a[0][2], a[0][3], b2, b3);
            MMA_F16(C[1][2*pr],   a[1][0], a[1][1], a[1][2], a[1][3], b0, b1);
            MMA_F16(C[1][2*pr+1], a[1][0], a[1][1], a[1][2], a[1][3], b2, b3);
        }
        __syncthreads();
    }
}

// ---------------------------------------------------------------------------
// mm3: out[w] = X @ W[w] + bias[w]   (fp16 MMA, BM=128, double-buffered)
// Grid = (3, rowTiles): blockIdx.x = weight set (fastest dim) so the three
// blocks reading the same X tile are schedule-adjacent -> X hits L2 twice.
// ---------------------------------------------------------------------------
__global__ void __launch_bounds__(256)
mm3_kernel(const float* __restrict__ X, int ldx, int M, int K,
           const float* __restrict__ W0, const float* __restrict__ W1, const float* __restrict__ W2,
           const float* __restrict__ b0, const float* __restrict__ b1, const float* __restrict__ b2,
           float* __restrict__ o0, float* __restrict__ o1, float* __restrict__ o2)
{
    __shared__ __align__(16) __half Xs[2][128][24];   // stride 48B, conflict-free ldsm
    __shared__ __align__(16) __half Ws[2][16][136];   // stride 272B

    const float* W   = (blockIdx.x == 0) ? W0 : (blockIdx.x == 1) ? W1 : W2;
    const float* bia = (blockIdx.x == 0) ? b0 : (blockIdx.x == 1) ? b1 : b2;
    float*       out = (blockIdx.x == 0) ? o0 : (blockIdx.x == 1) ? o1 : o2;

    const int tid = threadIdx.x, warp = tid >> 5, lane = tid & 31;
    const int gid = lane >> 2, tig = lane & 3;
    const int wr = (warp >> 1) * 32, wc = (warp & 1) * 64;
    const int brow = blockIdx.y * 128;

    const int xrow = tid >> 1, xcb = (tid & 1) * 8;
    const int wrow = tid >> 4, wcb = (tid & 15) * 8;
    const int xgr  = brow + xrow;

    const unsigned xs0 = (unsigned)__cvta_generic_to_shared(&Xs[0][0][0]);
    const unsigned ws0 = (unsigned)__cvta_generic_to_shared(&Ws[0][0][0]);
    const int aRowOff = (wr + (lane & 15)) * 48 + ((lane >> 4) * 8) * 2;
    const int bAddr0  = ((lane & 7) + ((lane >> 3) & 1) * 8) * 272
                      + (wc + (lane >> 4) * 8) * 2;

    float C[2][8][4];
#pragma unroll
    for (int i = 0; i < 2; ++i)
#pragma unroll
        for (int j = 0; j < 8; ++j)
#pragma unroll
            for (int k = 0; k < 4; ++k) C[i][j][k] = 0.f;

    float4 xv0, xv1, wv0, wv1;

    // prefetch chunk 0
    xv0 = make_float4(0.f,0.f,0.f,0.f); xv1 = xv0;
    if (xgr < M) {
        const float* p = X + (size_t)xgr * ldx + xcb;
        xv0 = *(const float4*)p; xv1 = *(const float4*)(p + 4);
    }
    {
        const float* wp = W + (size_t)wrow * H + wcb;
        wv0 = *(const float4*)wp; wv1 = *(const float4*)(wp + 4);
    }
    {
        uint4 xw; xw.x = pk(xv0.x,xv0.y); xw.y = pk(xv0.z,xv0.w);
                  xw.z = pk(xv1.x,xv1.y); xw.w = pk(xv1.z,xv1.w);
        *(uint4*)&Xs[0][xrow][xcb] = xw;
        uint4 ww; ww.x = pk(wv0.x,wv0.y); ww.y = pk(wv0.z,wv0.w);
                  ww.z = pk(wv1.x,wv1.y); ww.w = pk(wv1.z,wv1.w);
        *(uint4*)&Ws[0][wrow][wcb] = ww;
    }
    __syncthreads();

    const int nk = K >> 4;
    for (int it = 0; it < nk; ++it) {
        const int buf = it & 1;
        // LDG next chunk (latency hidden under compute)
        if (it + 1 < nk) {
            const int k0 = (it + 1) << 4;
            xv0 = make_float4(0.f,0.f,0.f,0.f); xv1 = xv0;
            if (xgr < M) {
                const float* p = X + (size_t)xgr * ldx + k0 + xcb;
                xv0 = *(const float4*)p; xv1 = *(const float4*)(p + 4);
            }
            const float* wp = W + (size_t)(k0 + wrow) * H + wcb;
            wv0 = *(const float4*)wp; wv1 = *(const float4*)(wp + 4);
        }
        // compute on buf
        {
            const unsigned xb = xs0 + buf * 6144;
            const unsigned wb = ws0 + buf * 4352;
            unsigned a[2][4];
#pragma unroll
            for (int mi = 0; mi < 2; ++mi)
                LDSM_X4(a[mi][0], a[mi][1], a[mi][2], a[mi][3],
                        xb + aRowOff + mi * 16 * 48);
#pragma unroll
            for (int pr = 0; pr < 4; ++pr) {
                unsigned bb0, bb1, bb2, bb3;
                LDSM_X4_T(bb0, bb1, bb2, bb3, wb + bAddr0 + pr * 32);
                MMA_F16(C[0][2*pr],   a[0][0], a[0][1], a[0][2], a[0][3], bb0, bb1);
                MMA_F16(C[0][2*pr+1], a[0][0], a[0][1], a[0][2], a[0][3], bb2, bb3);
                MMA_F16(C[1][2*pr],   a[1][0], a[1][1], a[1][2], a[1][3], bb0, bb1);
                MMA_F16(C[1][2*pr+1], a[1][0], a[1][1], a[1][2], a[1][3], bb2, bb3);
            }
        }
        // STS next chunk into other buffer
        if (it + 1 < nk) {
            const int nb = buf ^ 1;
            uint4 xw; xw.x = pk(xv0.x,xv0.y); xw.y = pk(xv0.z,xv0.w);
                      xw.z = pk(xv1.x,xv1.y); xw.w = pk(xv1.z,xv1.w);
            *(uint4*)&Xs[nb][xrow][xcb] = xw;
            uint4 ww; ww.x = pk(wv0.x,wv0.y); ww.y = pk(wv0.z,wv0.w);
                      ww.z = pk(wv1.x,wv1.y); ww.w = pk(wv1.z,wv1.w);
            *(uint4*)&Ws[nb][wrow][wcb] = ww;
        }
        __syncthreads();
    }

#pragma unroll
    for (int mi = 0; mi < 2; ++mi)
#pragma unroll
        for (int ni = 0; ni < 8; ++ni) {
            const int col = wc + ni * 8 + 2 * tig;
            const float bx = bia ? bia[col] : 0.f;
            const float by = bia ? bia[col + 1] : 0.f;
            const int r0 = brow + wr + mi * 16 + gid;
            const int r1 = r0 + 8;
            if (r0 < M) *(float2*)&out[(size_t)r0 * H + col] =
                make_float2(C[mi][ni][0] + bx, C[mi][ni][1] + by);
            if (r1 < M) *(float2*)&out[(size_t)r1 * H + col] =
                make_float2(C[mi][ni][2] + bx, C[mi][ni][3] + by);
        }
}

// ---------------------------------------------------------------------------
// fused_iter1: h = sigmoid(Pz)*tanh(Ph) -> global + smem(half); q = h @ Ur.
// BM=64, warps 2x4 (warp tile 32x32, NT=4).
// ---------------------------------------------------------------------------
__global__ void __launch_bounds__(256)
fused_iter1_kernel(const float* __restrict__ Pz, const float* __restrict__ Ph,
                   const float* __restrict__ Ur,
                   float* __restrict__ h_out, float* __restrict__ q_out, int E)
{
    __shared__ __align__(16) __half As[64][136];
    __shared__ __align__(16) __half Wb[16][136];

    const int tid = threadIdx.x, lane = tid & 31, ty = tid >> 5;
    const int gid = lane >> 2, tig = lane & 3;
    const int wr = (ty >> 2) * 32, wc = (ty & 3) * 32;
    const int brow = blockIdx.x * 64;
    const int c4 = lane * 4;

    const unsigned AsB = (unsigned)__cvta_generic_to_shared(&As[0][0]);
    const unsigned WbB = (unsigned)__cvta_generic_to_shared(&Wb[0][0]);

#pragma unroll
    for (int pass = 0; pass < 8; ++pass) {
        const int er = pass * 8 + ty;
        const int e  = brow + er;
        float4 v = make_float4(0.f,0.f,0.f,0.f);
        if (e < E) {
            const float4 pz = *(const float4*)&Pz[(size_t)e*H + c4];
            const float4 ph = *(const float4*)&Ph[(size_t)e*H + c4];
            v.x = sigmoidf_(pz.x) * tanhf(ph.x);
            v.y = sigmoidf_(pz.y) * tanhf(ph.y);
            v.z = sigmoidf_(pz.z) * tanhf(ph.z);
            v.w = sigmoidf_(pz.w) * tanhf(ph.w);
            if (e == 0) v = make_float4(0.f,0.f,0.f,0.f);
            *(float4*)&h_out[(size_t)e*H + c4] = v;
        }
        uint2 hv; hv.x = pk(v.x, v.y); hv.y = pk(v.z, v.w);
        *(uint2*)&As[er][c4] = hv;
    }
    __syncthreads();

    float C[2][4][4];
#pragma unroll
    for (int i = 0; i < 2; ++i)
#pragma unroll
        for (int j = 0; j < 4; ++j)
#pragma unroll
            for (int k = 0; k < 4; ++k) C[i][j][k] = 0.f;
    gemm_smemA_f16<4>(AsB, Ur, Wb, WbB, C, wr, wc, lane, tid);

#pragma unroll
    for (int mi = 0; mi < 2; ++mi)
#pragma unroll
        for (int ni = 0; ni < 4; ++ni) {
            const int col = wc + ni * 8 + 2 * tig;
            const int r0 = brow + wr + mi * 16 + gid;
            const int r1 = r0 + 8;
            if (r0 < E) *(float2*)&q_out[(size_t)r0 * H + col] =
                make_float2(C[mi][ni][0], C[mi][ni][1]);
            if (r1 < E) *(float2*)&q_out[(size_t)r1 * H + col] =
                make_float2(C[mi][ni][2], C[mi][ni][3]);
        }
}

// ---------------------------------------------------------------------------
// fused_gru (R10 proven config): BM=32, warps 1x8 (warp tile 32x16, NT=2).
// gather(sh,sg) -> smem(half); Cz=sh@Wz2, Ch=sg@Wh2; GRU epilogue -> h_out +
// smem(half); optional q_out = h_new @ Ur.
// ---------------------------------------------------------------------------
__global__ void __launch_bounds__(256)
fused_gru_kernel(const float* __restrict__ h_in, const float* __restrict__ q_in,
                 const int* __restrict__ bg,
                 const float* __restrict__ Pr, const float* __restrict__ Pz,
                 const float* __restrict__ Ph,
                 const float* __restrict__ Wz2, const float* __restrict__ Wh2,
                 const float* __restrict__ Ur,
                 float* __restrict__ h_out, float* __restrict__ q_out,
                 int E, int do_q)
{
    __shared__ __align__(16) __half SHs[32][136];
    __shared__ __align__(16) __half SGs[32][136];
    __shared__ __align__(16) __half Wb[16][136];

    const int tid = threadIdx.x, lane = tid & 31, ty = tid >> 5;
    const int gid = lane >> 2, tig = lane & 3;
    const int wc = ty * 16;
    const int brow = blockIdx.x * 32;
    const int c4 = lane * 4;

    const unsigned SHB = (unsigned)__cvta_generic_to_shared(&SHs[0][0]);
    const unsigned SGB = (unsigned)__cvta_generic_to_shared(&SGs[0][0]);
    const unsigned WbB = (unsigned)__cvta_generic_to_shared(&Wb[0][0]);

#pragma unroll
    for (int pass = 0; pass < 4; ++pass) {
        const int er = pass * 8 + ty;
        const int e  = brow + er;
        float4 sh = make_float4(0.f,0.f,0.f,0.f);
        float4 sg = make_float4(0.f,0.f,0.f,0.f);
        if (e < E) {
            const float4 pr = *(const float4*)&Pr[(size_t)e*H + c4];
#pragma unroll
            for (int j = 0; j < 6; ++j) {
                const int idx = __ldg(&bg[e * 6 + j]);
                const float4 hn = *(const float4*)&h_in[(size_t)idx*H + c4];
                const float4 qn = *(const float4*)&q_in[(size_t)idx*H + c4];
                sh.x += hn.x; sh.y += hn.y; sh.z += hn.z; sh.w += hn.w;
                sg.x += hn.x * sigmoidf_(pr.x + qn.x);
                sg.y += hn.y * sigmoidf_(pr.y + qn.y);
                sg.z += hn.z * sigmoidf_(pr.z + qn.z);
                sg.w += hn.w * sigmoidf_(pr.w + qn.w);
            }
        }
        uint2 a; a.x = pk(sh.x, sh.y); a.y = pk(sh.z, sh.w);
        *(uint2*)&SHs[er][c4] = a;
        uint2 b; b.x = pk(sg.x, sg.y); b.y = pk(sg.z, sg.w);
        *(uint2*)&SGs[er][c4] = b;
    }

    float Cz[2][2][4], Ch[2][2][4];
#pragma unroll
    for (int i = 0; i < 2; ++i)
#pragma unroll
        for (int j = 0; j < 2; ++j)
#pragma unroll
            for (int k = 0; k < 4; ++k) { Cz[i][j][k] = 0.f; Ch[i][j][k] = 0.f; }

    gemm_smemA_f16<2>(SHB, Wz2, Wb, WbB, Cz, 0, wc, lane, tid);
    gemm_smemA_f16<2>(SGB, Wh2, Wb, WbB, Ch, 0, wc, lane, tid);

#pragma unroll
    for (int mi = 0; mi < 2; ++mi)
#pragma unroll
        for (int ni = 0; ni < 2; ++ni) {
            const int col = wc + ni * 8 + 2 * tig;
#pragma unroll
            for (int half = 0; half < 2; ++half) {
                const int lr  = mi * 16 + gid + half * 8;
                const int row = brow + lr;
                if (row >= E) continue;
                const size_t base = (size_t)row * H + col;
                const float2 pz = *(const float2*)&Pz[base];
                const float2 ph = *(const float2*)&Ph[base];
                const float sh0 = __half2float(SHs[lr][col]);
                const float sh1 = __half2float(SHs[lr][col + 1]);
                const float z0 = sigmoidf_(Cz[mi][ni][half*2+0] + pz.x);
                const float z1 = sigmoidf_(Cz[mi][ni][half*2+1] + pz.y);
                const float p0 = tanhf(Ch[mi][ni][half*2+0] + ph.x);
                const float p1 = tanhf(Ch[mi][ni][half*2+1] + ph.y);
                float o0 = (1.f - z0) * sh0 + z0 * p0;
                float o1 = (1.f - z1) * sh1 + z1 * p1;
                if (row == 0) { o0 = 0.f; o1 = 0.f; }
                *(float2*)&h_out[base] = make_float2(o0, o1);
                *(unsigned*)&SHs[lr][col] = pk(o0, o1);
            }
        }
    if (!do_q) return;
    __syncthreads();

    float Cq[2][2][4];
#pragma unroll
    for (int i = 0; i < 2; ++i)
#pragma unroll
        for (int j = 0; j < 2; ++j)
#pragma unroll
            for (int k = 0; k < 4; ++k) Cq[i][j][k] = 0.f;
    gemm_smemA_f16<2>(SHB, Ur, Wb, WbB, Cq, 0, wc, lane, tid);

#pragma unroll
    for (int mi = 0; mi < 2; ++mi)
#pragma unroll
        for (int ni = 0; ni < 2; ++ni) {
            const int col = wc + ni * 8 + 2 * tig;
            const int r0 = brow + mi * 16 + gid;
            const int r1 = r0 + 8;
            if (r0 < E) *(float2*)&q_out[(size_t)r0 * H + col] =
                make_float2(Cq[mi][ni][0], Cq[mi][ni][1]);
            if (r1 < E) *(float2*)&q_out[(size_t)r1 * H + col] =
                make_float2(Cq[mi][ni][2], Cq[mi][ni][3]);
        }
}

// ---------------------------------------------------------------------------
// fused_node: BM=64, warps 2x4 (NT=4).
// C = fnode @ Wo[0:256] + gather(nei) @ Wo[256:384]; relu(+bo), row0 mask.
// ---------------------------------------------------------------------------
__global__ void __launch_bounds__(256)
fused_node_kernel(const float* __restrict__ fnode, const float* __restrict__ Wo,
                  const float* __restrict__ h, const int* __restrict__ ag,
                  const float* __restrict__ bo, float* __restrict__ out, int N)
{
    __shared__ __align__(16) __half As[64][136];
    __shared__ __align__(16) __half Wb[16][136];

    const int tid = threadIdx.x, lane = tid & 31, ty = tid >> 5;
    const int gid = lane >> 2, tig = lane & 3;
    const int wr = (ty >> 2) * 32, wc = (ty & 3) * 32;
    const int brow = blockIdx.x * 64;
    const int c4 = lane * 4;

    const unsigned AsB = (unsigned)__cvta_generic_to_shared(&As[0][0]);
    const unsigned WbB = (unsigned)__cvta_generic_to_shared(&Wb[0][0]);
    const int aRowOff = (wr + (lane & 15)) * 272 + ((lane >> 4) * 8) * 2;
    const int bAddr0  = ((lane & 7) + ((lane >> 3) & 1) * 8) * 272
                      + (wc + (lane >> 4) * 8) * 2;
    const int wrow = tid >> 4, wcb = (tid & 15) * 8;

    float C[2][4][4];
#pragma unroll
    for (int i = 0; i < 2; ++i)
#pragma unroll
        for (int j = 0; j < 4; ++j)
#pragma unroll
            for (int k = 0; k < 4; ++k) C[i][j][k] = 0.f;

    // phase A: fnode @ Wo[0:256], per-chunk staging into As cols [0,16)
    for (int k0 = 0; k0 < 256; k0 += 16) {
        {
            const int row = tid >> 2, cb = (tid & 3) * 4;
            const int gr  = brow + row;
            float4 v = make_float4(0.f,0.f,0.f,0.f);
            if (gr < N) v = *(const float4*)&fnode[(size_t)gr * 256 + k0 + cb];
            uint2 hv; hv.x = pk(v.x, v.y); hv.y = pk(v.z, v.w);
            *(uint2*)&As[row][cb] = hv;
        }
        {
            const float* p = Wo + (size_t)(k0 + wrow) * H + wcb;
            const float4 v0 = *(const float4*)p, v1 = *(const float4*)(p + 4);
            uint4 w;
            w.x = pk(v0.x, v0.y); w.y = pk(v0.z, v0.w);
            w.z = pk(v1.x, v1.y); w.w = pk(v1.z, v1.w);
            *(uint4*)&Wb[wrow][wcb] = w;
        }
        __syncthreads();
        unsigned a[2][4];
#pragma unroll
        for (int mi = 0; mi < 2; ++mi)
            LDSM_X4(a[mi][0], a[mi][1], a[mi][2], a[mi][3],
                    AsB + aRowOff + mi * 16 * 272);
#pragma unroll
        for (int pr = 0; pr < 2; ++pr) {
            unsigned bb0, bb1, bb2, bb3;
            LDSM_X4_T(bb0, bb1, bb2, bb3, WbB + bAddr0 + pr * 32);
            MMA_F16(C[0][2*pr],   a[0][0], a[0][1], a[0][2], a[0][3], bb0, bb1);
            MMA_F16(C[0][2*pr+1], a[0][0], a[0][1], a[0][2], a[0][3], bb2, bb3);
            MMA_F16(C[1][2*pr],   a[1][0], a[1][1], a[1][2], a[1][3], bb0, bb1);
            MMA_F16(C[1][2*pr+1], a[1][0], a[1][1], a[1][2], a[1][3], bb2, bb3);
        }
        __syncthreads();
    }

    // phase B: gather nei into As (full width, half)
#pragma unroll
    for (int pass = 0; pass < 8; ++pass) {
        const int nr = pass * 8 + ty;
        const int n  = brow + nr;
        float4 s = make_float4(0.f,0.f,0.f,0.f);
        if (n < N) {
#pragma unroll
            for (int j = 0; j < 6; ++j) {
                const int idx = __ldg(&ag[n * 6 + j]);
                const float4 hn = *(const float4*)&h[(size_t)idx*H + c4];
                s.x += hn.x; s.y += hn.y; s.z += hn.z; s.w += hn.w;
            }
        }
        uint2 hv; hv.x = pk(s.x, s.y); hv.y = pk(s.z, s.w);
        *(uint2*)&As[nr][c4] = hv;
    }
    __syncthreads();

    gemm_smemA_f16<4>(AsB, Wo + 256 * H, Wb, WbB, C, wr, wc, lane, tid);

#pragma unroll
    for (int mi = 0; mi < 2; ++mi)
#pragma unroll
        for (int ni = 0; ni < 4; ++ni) {
            const int col = wc + ni * 8 + 2 * tig;
            const float bx = bo[col], by = bo[col + 1];
#pragma unroll
            for (int half = 0; half < 2; ++half) {
                const int row = brow + wr + mi * 16 + gid + half * 8;
                if (row >= N) continue;
                float o0 = fmaxf(C[mi][ni][half*2+0] + bx, 0.f);
                float o1 = fmaxf(C[mi][ni][half*2+1] + by, 0.f);
                if (row == 0) { o0 = 0.f; o1 = 0.f; }
                *(float2*)&out[(size_t)row * H + col] = make_float2(o0, o1);
            }
        }
}

// ---------------------------------------------------------------------------
extern "C" void kernel_launch(void* const* d_in, const int* in_sizes, int n_in,
                              void* d_out, int out_size)
{
    const float* fnode  = (const float*) d_in[0];
    const float* fmess  = (const float*) d_in[1];
    const void*  agraph = d_in[2];
    const void*  bgraph = d_in[3];
    const float* Wz     = (const float*) d_in[4];
    const float* bz     = (const float*) d_in[5];
    const float* Wr     = (const float*) d_in[6];
    const float* Ur     = (const float*) d_in[7];
    const float* bur    = (const float*) d_in[8];
    const float* Wh     = (const float*) d_in[9];
    const float* bh     = (const float*) d_in[10];
    const float* Wo     = (const float*) d_in[11];
    const float* bo     = (const float*) d_in[12];

    const int N = in_sizes[2] / 6;
    const int E = in_sizes[3] / 6;

    float *Pz, *Pr, *Ph, *q1, *q2, *hA, *hB;
    int *bg32, *ag32;
    cudaGetSymbolAddress((void**)&Pz,   g_Pz);
    cudaGetSymbolAddress((void**)&Pr,   g_Pr);
    cudaGetSymbolAddress((void**)&Ph,   g_Ph);
    cudaGetSymbolAddress((void**)&q1,   g_q1);
    cudaGetSymbolAddress((void**)&q2,   g_q2);
    cudaGetSymbolAddress((void**)&hA,   g_hA);
    cudaGetSymbolAddress((void**)&hB,   g_hB);
    cudaGetSymbolAddress((void**)&bg32, g_bg32);
    cudaGetSymbolAddress((void**)&ag32, g_ag32);

    float* out_node = (float*)d_out;
    const long long need = (long long)(N + E) * H;
    const bool out_has_h = ((long long)out_size >= need);
    float* h_final = out_has_h ? ((float*)d_out + (size_t)N * H) : hA;

    detect_idx_kernel<<<1, 1>>>((const unsigned int*)bgraph);
    convert_idx_kernel<<<(E * 6 + 255) / 256, 256>>>(bgraph, bg32, E * 6);
    convert_idx_kernel<<<(N * 6 + 255) / 256, 256>>>(agraph, ag32, N * 6);

    const int gE128 = (E + 127) / 128;
    const int gE64  = (E + 63) / 64;
    const int gE32  = (E + 31) / 32;
    const int gN64  = (N + 63) / 64;

    // loop-invariant precompute; weight-set on blockIdx.x for L2 reuse of X
    mm3_kernel<<<dim3(3, gE128), 256>>>(fmess, 384, E, 384,
                                        Wz, Wr, Wh, bz, bur, bh, Pz, Pr, Ph);

    // iteration 1 (h=0): elementwise h + fused q = h@Ur
    fused_iter1_kernel<<<gE64, 256>>>(Pz, Ph, Ur, hA, q1, E);

    // iteration 2: gather + dual GEMM + GRU + fused q
    fused_gru_kernel<<<gE32, 256>>>(hA, q1, bg32, Pr, Pz, Ph,
                                    Wz + 384 * H, Wh + 384 * H, Ur, hB, q2, E, 1);

    // iteration 3: final h (no q needed)
    fused_gru_kernel<<<gE32, 256>>>(hB, q2, bg32, Pr, Pz, Ph,
                                    Wz + 384 * H, Wh + 384 * H, Ur, h_final, q1, E, 0);

    // output head: fused gather + dual-segment GEMM
    fused_node_kernel<<<gN64, 256>>>(fnode, Wo, h_final, ag32, bo, out_node, N);
}

// round 13
// speedup vs baseline: 1.3912x; 1.1431x over previous
#include <cuda_runtime.h>
#include <cuda_fp16.h>
#include <math.h>

#define H 128
#define E_MAX 80000
#define N_MAX 40000

// ---------------- scratch (device globals; no allocation allowed) ----------
__device__ __align__(16) float  g_Pz [E_MAX * H];
__device__ __align__(16) float  g_Pr [E_MAX * H];
__device__ __align__(16) float  g_Ph [E_MAX * H];
__device__ __align__(16) float  g_hF [E_MAX * H];       // fp32 h sink when d_out lacks h
__device__ __align__(16) __half g_fm16[E_MAX * 384];    // fmess fp16
__device__ __align__(16) __half g_fn16[N_MAX * 256];    // fnode fp16
__device__ __align__(16) __half g_hA16[E_MAX * H];
__device__ __align__(16) __half g_hB16[E_MAX * H];
__device__ __align__(16) __half g_q116[E_MAX * H];
__device__ __align__(16) __half g_q216[E_MAX * H];
__device__ __align__(16) __half g_Wz16[512 * H];
__device__ __align__(16) __half g_Wr16[384 * H];
__device__ __align__(16) __half g_Wh16[512 * H];
__device__ __align__(16) __half g_Ur16[H * H];
__device__ __align__(16) __half g_Wo16[384 * H];
__device__ int g_bg32[E_MAX * 6];
__device__ int g_ag32[N_MAX * 6];
__device__ int g_idx_is64;

__device__ __forceinline__ float sigmoidf_(float x) { return 1.0f / (1.0f + expf(-x)); }
__device__ __forceinline__ unsigned pk(float a, float b) {
    __half2 h = __floats2half2_rn(a, b);
    return *reinterpret_cast<unsigned*>(&h);
}
__device__ __forceinline__ float2 up(unsigned u) {
    return __half22float2(*reinterpret_cast<__half2*>(&u));
}

#define MMA_F16(C, A0,A1,A2,A3, B0,B1) \
    asm volatile("mma.sync.aligned.m16n8k16.row.col.f32.f16.f16.f32 " \
        "{%0,%1,%2,%3},{%4,%5,%6,%7},{%8,%9},{%0,%1,%2,%3};" \
        : "+f"((C)[0]), "+f"((C)[1]), "+f"((C)[2]), "+f"((C)[3]) \
        : "r"(A0), "r"(A1), "r"(A2), "r"(A3), "r"(B0), "r"(B1))

#define LDSM_X4(R0,R1,R2,R3,ADDR) \
    asm volatile("ldmatrix.sync.aligned.m8n8.x4.shared.b16 {%0,%1,%2,%3}, [%4];" \
        : "=r"(R0), "=r"(R1), "=r"(R2), "=r"(R3) : "r"(ADDR))

#define LDSM_X4_T(R0,R1,R2,R3,ADDR) \
    asm volatile("ldmatrix.sync.aligned.m8n8.x4.trans.shared.b16 {%0,%1,%2,%3}, [%4];" \
        : "=r"(R0), "=r"(R1), "=r"(R2), "=r"(R3) : "r"(ADDR))

// ---------------------------------------------------------------------------
// prep kernels
// ---------------------------------------------------------------------------
__global__ void detect_idx_kernel(const unsigned int* __restrict__ w)
{
    g_idx_is64 = (w[1] == 0u && w[3] == 0u && w[5] == 0u && w[7] == 0u) ? 1 : 0;
}
__global__ void convert_idx_kernel(const void* __restrict__ src, int* __restrict__ dst, int n)
{
    int i = blockIdx.x * blockDim.x + threadIdx.x;
    if (i >= n) return;
    if (g_idx_is64) dst[i] = (int)((const long long*)src)[i];
    else            dst[i] = ((const int*)src)[i];
}
__global__ void f32_to_f16_kernel(const float* __restrict__ src, __half* __restrict__ dst, int n4)
{
    int i = blockIdx.x * blockDim.x + threadIdx.x;
    if (i >= n4) return;
    const float4 v = ((const float4*)src)[i];
    uint2 o; o.x = pk(v.x, v.y); o.y = pk(v.z, v.w);
    ((uint2*)dst)[i] = o;
}

// ---------------------------------------------------------------------------
// fp16 GEMM helper: A resident in smem as halves [rows][136] (stride 272B),
// C += A[.., 0:128] @ W[0:128, 0:128] (W fp16 in gmem).
// ---------------------------------------------------------------------------
template<int NT>
__device__ __forceinline__ void gemm_smemA_f16(
    unsigned AsB, const __half* __restrict__ W,
    __half (*Wb)[136], unsigned WbB,
    float (&C)[2][NT][4],
    int wr, int wc, int lane, int tid)
{
    const int aRowOff = (wr + (lane & 15)) * 272 + ((lane >> 4) * 8) * 2;
    const int bAddr0  = ((lane & 7) + ((lane >> 3) & 1) * 8) * 272
                      + (wc + (lane >> 4) * 8) * 2;
    const int wrow = tid >> 4, wcb = (tid & 15) * 8;

    for (int k0 = 0; k0 < 128; k0 += 16) {
        *(uint4*)&Wb[wrow][wcb] = *(const uint4*)&W[(size_t)(k0 + wrow) * H + wcb];
        __syncthreads();

        unsigned a[2][4];
#pragma unroll
        for (int mi = 0; mi < 2; ++mi)
            LDSM_X4(a[mi][0], a[mi][1], a[mi][2], a[mi][3],
                    AsB + aRowOff + mi * 16 * 272 + k0 * 2);
#pragma unroll
        for (int pr = 0; pr < NT / 2; ++pr) {
            unsigned b0, b1, b2, b3;
            LDSM_X4_T(b0, b1, b2, b3, WbB + bAddr0 + pr * 32);
            MMA_F16(C[0][2*pr],   a[0][0], a[0][1], a[0][2], a[0][3], b0, b1);
            MMA_F16(C[0][2*pr+1], a[0][0], a[0][1], a[0][2], a[0][3], b2, b3);
            MMA_F16(C[1][2*pr],   a[1][0], a[1][1], a[1][2], a[1][3], b0, b1);
            MMA_F16(C[1][2*pr+1], a[1][0], a[1][1], a[1][2], a[1][3], b2, b3);
        }
        __syncthreads();
    }
}

// ---------------------------------------------------------------------------
// mm3: out[w] = X @ W[w] + bias[w]  (X, W fp16; BM=128, double-buffered)
// Grid = (3, rowTiles): weight set on blockIdx.x -> X tiles hit L2.
// ---------------------------------------------------------------------------
__global__ void __launch_bounds__(256)
mm3_kernel(const __half* __restrict__ X, int ldx, int M, int K,
           const __half* __restrict__ W0, const __half* __restrict__ W1, const __half* __restrict__ W2,
           const float* __restrict__ b0, const float* __restrict__ b1, const float* __restrict__ b2,
           float* __restrict__ o0, float* __restrict__ o1, float* __restrict__ o2)
{
    __shared__ __align__(16) __half Xs[2][128][24];
    __shared__ __align__(16) __half Ws[2][16][136];

    const __half* W  = (blockIdx.x == 0) ? W0 : (blockIdx.x == 1) ? W1 : W2;
    const float* bia = (blockIdx.x == 0) ? b0 : (blockIdx.x == 1) ? b1 : b2;
    float*       out = (blockIdx.x == 0) ? o0 : (blockIdx.x == 1) ? o1 : o2;

    const int tid = threadIdx.x, warp = tid >> 5, lane = tid & 31;
    const int gid = lane >> 2, tig = lane & 3;
    const int wr = (warp >> 1) * 32, wc = (warp & 1) * 64;
    const int brow = blockIdx.y * 128;

    const int xrow = tid >> 1, xcb = (tid & 1) * 8;
    const int wrow = tid >> 4, wcb = (tid & 15) * 8;
    const int xgr  = brow + xrow;

    const unsigned xs0 = (unsigned)__cvta_generic_to_shared(&Xs[0][0][0]);
    const unsigned ws0 = (unsigned)__cvta_generic_to_shared(&Ws[0][0][0]);
    const int aRowOff = (wr + (lane & 15)) * 48 + ((lane >> 4) * 8) * 2;
    const int bAddr0  = ((lane & 7) + ((lane >> 3) & 1) * 8) * 272
                      + (wc + (lane >> 4) * 8) * 2;

    float C[2][8][4];
#pragma unroll
    for (int i = 0; i < 2; ++i)
#pragma unroll
        for (int j = 0; j < 8; ++j)
#pragma unroll
            for (int k = 0; k < 4; ++k) C[i][j][k] = 0.f;

    uint4 xw = make_uint4(0,0,0,0), ww;

    // prefetch chunk 0
    if (xgr < M) xw = *(const uint4*)&X[(size_t)xgr * ldx + xcb];
    ww = *(const uint4*)&W[(size_t)wrow * H + wcb];
    *(uint4*)&Xs[0][xrow][xcb] = xw;
    *(uint4*)&Ws[0][wrow][wcb] = ww;
    __syncthreads();

    const int nk = K >> 4;
    for (int it = 0; it < nk; ++it) {
        const int buf = it & 1;
        if (it + 1 < nk) {
            const int k0 = (it + 1) << 4;
            xw = make_uint4(0,0,0,0);
            if (xgr < M) xw = *(const uint4*)&X[(size_t)xgr * ldx + k0 + xcb];
            ww = *(const uint4*)&W[(size_t)(k0 + wrow) * H + wcb];
        }
        {
            const unsigned xb = xs0 + buf * 6144;
            const unsigned wb = ws0 + buf * 4352;
            unsigned a[2][4];
#pragma unroll
            for (int mi = 0; mi < 2; ++mi)
                LDSM_X4(a[mi][0], a[mi][1], a[mi][2], a[mi][3],
                        xb + aRowOff + mi * 16 * 48);
#pragma unroll
            for (int pr = 0; pr < 4; ++pr) {
                unsigned bb0, bb1, bb2, bb3;
                LDSM_X4_T(bb0, bb1, bb2, bb3, wb + bAddr0 + pr * 32);
                MMA_F16(C[0][2*pr],   a[0][0], a[0][1], a[0][2], a[0][3], bb0, bb1);
                MMA_F16(C[0][2*pr+1], a[0][0], a[0][1], a[0][2], a[0][3], bb2, bb3);
                MMA_F16(C[1][2*pr],   a[1][0], a[1][1], a[1][2], a[1][3], bb0, bb1);
                MMA_F16(C[1][2*pr+1], a[1][0], a[1][1], a[1][2], a[1][3], bb2, bb3);
            }
        }
        if (it + 1 < nk) {
            const int nb = buf ^ 1;
            *(uint4*)&Xs[nb][xrow][xcb] = xw;
            *(uint4*)&Ws[nb][wrow][wcb] = ww;
        }
        __syncthreads();
    }

#pragma unroll
    for (int mi = 0; mi < 2; ++mi)
#pragma unroll
        for (int ni = 0; ni < 8; ++ni) {
            const int col = wc + ni * 8 + 2 * tig;
            const float bx = bia ? bia[col] : 0.f;
            const float by = bia ? bia[col + 1] : 0.f;
            const int r0 = brow + wr + mi * 16 + gid;
            const int r1 = r0 + 8;
            if (r0 < M) *(float2*)&out[(size_t)r0 * H + col] =
                make_float2(C[mi][ni][0] + bx, C[mi][ni][1] + by);
            if (r1 < M) *(float2*)&out[(size_t)r1 * H + col] =
                make_float2(C[mi][ni][2] + bx, C[mi][ni][3] + by);
        }
}

// ---------------------------------------------------------------------------
// fused_iter1: h = sigmoid(Pz)*tanh(Ph) -> fp16 global + smem; q16 = h @ Ur.
// BM=64, warps 2x4 (NT=4).
// ---------------------------------------------------------------------------
__global__ void __launch_bounds__(256)
fused_iter1_kernel(const float* __restrict__ Pz, const float* __restrict__ Ph,
                   const __half* __restrict__ Ur,
                   __half* __restrict__ h_out, __half* __restrict__ q_out, int E)
{
    __shared__ __align__(16) __half As[64][136];
    __shared__ __align__(16) __half Wb[16][136];

    const int tid = threadIdx.x, lane = tid & 31, ty = tid >> 5;
    const int gid = lane >> 2, tig = lane & 3;
    const int wr = (ty >> 2) * 32, wc = (ty & 3) * 32;
    const int brow = blockIdx.x * 64;
    const int c4 = lane * 4;

    const unsigned AsB = (unsigned)__cvta_generic_to_shared(&As[0][0]);
    const unsigned WbB = (unsigned)__cvta_generic_to_shared(&Wb[0][0]);

#pragma unroll
    for (int pass = 0; pass < 8; ++pass) {
        const int er = pass * 8 + ty;
        const int e  = brow + er;
        float4 v = make_float4(0.f,0.f,0.f,0.f);
        uint2 hv;
        if (e < E) {
            const float4 pz = *(const float4*)&Pz[(size_t)e*H + c4];
            const float4 ph = *(const float4*)&Ph[(size_t)e*H + c4];
            v.x = sigmoidf_(pz.x) * tanhf(ph.x);
            v.y = sigmoidf_(pz.y) * tanhf(ph.y);
            v.z = sigmoidf_(pz.z) * tanhf(ph.z);
            v.w = sigmoidf_(pz.w) * tanhf(ph.w);
            if (e == 0) v = make_float4(0.f,0.f,0.f,0.f);
            hv.x = pk(v.x, v.y); hv.y = pk(v.z, v.w);
            *(uint2*)&h_out[(size_t)e*H + c4] = hv;
        } else { hv.x = 0u; hv.y = 0u; }
        *(uint2*)&As[er][c4] = hv;
    }
    __syncthreads();

    float C[2][4][4];
#pragma unroll
    for (int i = 0; i < 2; ++i)
#pragma unroll
        for (int j = 0; j < 4; ++j)
#pragma unroll
            for (int k = 0; k < 4; ++k) C[i][j][k] = 0.f;
    gemm_smemA_f16<4>(AsB, Ur, Wb, WbB, C, wr, wc, lane, tid);

#pragma unroll
    for (int mi = 0; mi < 2; ++mi)
#pragma unroll
        for (int ni = 0; ni < 4; ++ni) {
            const int col = wc + ni * 8 + 2 * tig;
            const int r0 = brow + wr + mi * 16 + gid;
            const int r1 = r0 + 8;
            if (r0 < E) *(unsigned*)&q_out[(size_t)r0 * H + col] =
                pk(C[mi][ni][0], C[mi][ni][1]);
            if (r1 < E) *(unsigned*)&q_out[(size_t)r1 * H + col] =
                pk(C[mi][ni][2], C[mi][ni][3]);
        }
}

// ---------------------------------------------------------------------------
// fused_gru: BM=32, warps 1x8 (NT=2).  h/q in fp16; weights fp16.
// gather(sh,sg) -> smem; Cz=sh@Wz2, Ch=sg@Wh2; epilogue -> h16 (+h32 opt) +
// smem; optional q16 = h_new @ Ur.
// ---------------------------------------------------------------------------
__global__ void __launch_bounds__(256)
fused_gru_kernel(const __half* __restrict__ h_in, const __half* __restrict__ q_in,
                 const int* __restrict__ bg,
                 const float* __restrict__ Pr, const float* __restrict__ Pz,
                 const float* __restrict__ Ph,
                 const __half* __restrict__ Wz2, const __half* __restrict__ Wh2,
                 const __half* __restrict__ Ur,
                 __half* __restrict__ h16_out, float* __restrict__ h32_out,
                 __half* __restrict__ q_out,
                 int E, int do_q, int do_f32)
{
    __shared__ __align__(16) __half SHs[32][136];
    __shared__ __align__(16) __half SGs[32][136];
    __shared__ __align__(16) __half Wb[16][136];

    const int tid = threadIdx.x, lane = tid & 31, ty = tid >> 5;
    const int gid = lane >> 2, tig = lane & 3;
    const int wc = ty * 16;
    const int brow = blockIdx.x * 32;
    const int c4 = lane * 4;

    const unsigned SHB = (unsigned)__cvta_generic_to_shared(&SHs[0][0]);
    const unsigned SGB = (unsigned)__cvta_generic_to_shared(&SGs[0][0]);
    const unsigned WbB = (unsigned)__cvta_generic_to_shared(&Wb[0][0]);

#pragma unroll
    for (int pass = 0; pass < 4; ++pass) {
        const int er = pass * 8 + ty;
        const int e  = brow + er;
        float4 sh = make_float4(0.f,0.f,0.f,0.f);
        float4 sg = make_float4(0.f,0.f,0.f,0.f);
        if (e < E) {
            const float4 pr = *(const float4*)&Pr[(size_t)e*H + c4];
#pragma unroll
            for (int j = 0; j < 6; ++j) {
                const int idx = __ldg(&bg[e * 6 + j]);
                const uint2 hv = *(const uint2*)&h_in[(size_t)idx*H + c4];
                const uint2 qv = *(const uint2*)&q_in[(size_t)idx*H + c4];
                const float2 h01 = up(hv.x), h23 = up(hv.y);
                const float2 q01 = up(qv.x), q23 = up(qv.y);
                sh.x += h01.x; sh.y += h01.y; sh.z += h23.x; sh.w += h23.y;
                sg.x += h01.x * sigmoidf_(pr.x + q01.x);
                sg.y += h01.y * sigmoidf_(pr.y + q01.y);
                sg.z += h23.x * sigmoidf_(pr.z + q23.x);
                sg.w += h23.y * sigmoidf_(pr.w + q23.y);
            }
        }
        uint2 a; a.x = pk(sh.x, sh.y); a.y = pk(sh.z, sh.w);
        *(uint2*)&SHs[er][c4] = a;
        uint2 b; b.x = pk(sg.x, sg.y); b.y = pk(sg.z, sg.w);
        *(uint2*)&SGs[er][c4] = b;
    }

    float Cz[2][2][4], Ch[2][2][4];
#pragma unroll
    for (int i = 0; i < 2; ++i)
#pragma unroll
        for (int j = 0; j < 2; ++j)
#pragma unroll
            for (int k = 0; k < 4; ++k) { Cz[i][j][k] = 0.f; Ch[i][j][k] = 0.f; }

    gemm_smemA_f16<2>(SHB, Wz2, Wb, WbB, Cz, 0, wc, lane, tid);
    gemm_smemA_f16<2>(SGB, Wh2, Wb, WbB, Ch, 0, wc, lane, tid);

#pragma unroll
    for (int mi = 0; mi < 2; ++mi)
#pragma unroll
        for (int ni = 0; ni < 2; ++ni) {
            const int col = wc + ni * 8 + 2 * tig;
#pragma unroll
            for (int half = 0; half < 2; ++half) {
                const int lr  = mi * 16 + gid + half * 8;
                const int row = brow + lr;
                if (row >= E) continue;
                const size_t base = (size_t)row * H + col;
                const float2 pz = *(const float2*)&Pz[base];
                const float2 ph = *(const float2*)&Ph[base];
                const float sh0 = __half2float(SHs[lr][col]);
                const float sh1 = __half2float(SHs[lr][col + 1]);
                const float z0 = sigmoidf_(Cz[mi][ni][half*2+0] + pz.x);
                const float z1 = sigmoidf_(Cz[mi][ni][half*2+1] + pz.y);
                const float p0 = tanhf(Ch[mi][ni][half*2+0] + ph.x);
                const float p1 = tanhf(Ch[mi][ni][half*2+1] + ph.y);
                float o0 = (1.f - z0) * sh0 + z0 * p0;
                float o1 = (1.f - z1) * sh1 + z1 * p1;
                if (row == 0) { o0 = 0.f; o1 = 0.f; }
                const unsigned po = pk(o0, o1);
                *(unsigned*)&h16_out[base] = po;
                if (do_f32) *(float2*)&h32_out[base] = make_float2(o0, o1);
                *(unsigned*)&SHs[lr][col] = po;
            }
        }
    if (!do_q) return;
    __syncthreads();

    float Cq[2][2][4];
#pragma unroll
    for (int i = 0; i < 2; ++i)
#pragma unroll
        for (int j = 0; j < 2; ++j)
#pragma unroll
            for (int k = 0; k < 4; ++k) Cq[i][j][k] = 0.f;
    gemm_smemA_f16<2>(SHB, Ur, Wb, WbB, Cq, 0, wc, lane, tid);

#pragma unroll
    for (int mi = 0; mi < 2; ++mi)
#pragma unroll
        for (int ni = 0; ni < 2; ++ni) {
            const int col = wc + ni * 8 + 2 * tig;
            const int r0 = brow + mi * 16 + gid;
            const int r1 = r0 + 8;
            if (r0 < E) *(unsigned*)&q_out[(size_t)r0 * H + col] =
                pk(Cq[mi][ni][0], Cq[mi][ni][1]);
            if (r1 < E) *(unsigned*)&q_out[(size_t)r1 * H + col] =
                pk(Cq[mi][ni][2], Cq[mi][ni][3]);
        }
}

// ---------------------------------------------------------------------------
// fused_node: BM=64, warps 2x4 (NT=4).  fnode/Wo/h fp16.
// C = fnode @ Wo[0:256] + gather(nei) @ Wo[256:384]; relu(+bo), row0 mask.
// ---------------------------------------------------------------------------
__global__ void __launch_bounds__(256)
fused_node_kernel(const __half* __restrict__ fnode, const __half* __restrict__ Wo,
                  const __half* __restrict__ h, const int* __restrict__ ag,
                  const float* __restrict__ bo, float* __restrict__ out, int N)
{
    __shared__ __align__(16) __half As[64][136];
    __shared__ __align__(16) __half Wb[16][136];

    const int tid = threadIdx.x, lane = tid & 31, ty = tid >> 5;
    const int gid = lane >> 2, tig = lane & 3;
    const int wr = (ty >> 2) * 32, wc = (ty & 3) * 32;
    const int brow = blockIdx.x * 64;
    const int c4 = lane * 4;

    const unsigned AsB = (unsigned)__cvta_generic_to_shared(&As[0][0]);
    const unsigned WbB = (unsigned)__cvta_generic_to_shared(&Wb[0][0]);
    const int aRowOff = (wr + (lane & 15)) * 272 + ((lane >> 4) * 8) * 2;
    const int bAddr0  = ((lane & 7) + ((lane >> 3) & 1) * 8) * 272
                      + (wc + (lane >> 4) * 8) * 2;
    const int wrow = tid >> 4, wcb = (tid & 15) * 8;

    float C[2][4][4];
#pragma unroll
    for (int i = 0; i < 2; ++i)
#pragma unroll
        for (int j = 0; j < 4; ++j)
#pragma unroll
            for (int k = 0; k < 4; ++k) C[i][j][k] = 0.f;

    // phase A: fnode @ Wo[0:256], per-chunk staging into As cols [0,16)
    for (int k0 = 0; k0 < 256; k0 += 16) {
        {
            const int row = tid >> 2, cb = (tid & 3) * 4;
            const int gr  = brow + row;
            uint2 hv = make_uint2(0u, 0u);
            if (gr < N) hv = *(const uint2*)&fnode[(size_t)gr * 256 + k0 + cb];
            *(uint2*)&As[row][cb] = hv;
        }
        *(uint4*)&Wb[wrow][wcb] = *(const uint4*)&Wo[(size_t)(k0 + wrow) * H + wcb];
        __syncthreads();
        unsigned a[2][4];
#pragma unroll
        for (int mi = 0; mi < 2; ++mi)
            LDSM_X4(a[mi][0], a[mi][1], a[mi][2], a[mi][3],
                    AsB + aRowOff + mi * 16 * 272);
#pragma unroll
        for (int pr = 0; pr < 2; ++pr) {
            unsigned bb0, bb1, bb2, bb3;
            LDSM_X4_T(bb0, bb1, bb2, bb3, WbB + bAddr0 + pr * 32);
            MMA_F16(C[0][2*pr],   a[0][0], a[0][1], a[0][2], a[0][3], bb0, bb1);
            MMA_F16(C[0][2*pr+1], a[0][0], a[0][1], a[0][2], a[0][3], bb2, bb3);
            MMA_F16(C[1][2*pr],   a[1][0], a[1][1], a[1][2], a[1][3], bb0, bb1);
            MMA_F16(C[1][2*pr+1], a[1][0], a[1][1], a[1][2], a[1][3], bb2, bb3);
        }
        __syncthreads();
    }

    // phase B: gather nei into As (full width)
#pragma unroll
    for (int pass = 0; pass < 8; ++pass) {
        const int nr = pass * 8 + ty;
        const int n  = brow + nr;
        float4 s = make_float4(0.f,0.f,0.f,0.f);
        if (n < N) {
#pragma unroll
            for (int j = 0; j < 6; ++j) {
                const int idx = __ldg(&ag[n * 6 + j]);
                const uint2 hv = *(const uint2*)&h[(size_t)idx*H + c4];
                const float2 h01 = up(hv.x), h23 = up(hv.y);
                s.x += h01.x; s.y += h01.y; s.z += h23.x; s.w += h23.y;
            }
        }
        uint2 hv; hv.x = pk(s.x, s.y); hv.y = pk(s.z, s.w);
        *(uint2*)&As[nr][c4] = hv;
    }
    __syncthreads();

    gemm_smemA_f16<4>(AsB, Wo + 256 * H, Wb, WbB, C, wr, wc, lane, tid);

#pragma unroll
    for (int mi = 0; mi < 2; ++mi)
#pragma unroll
        for (int ni = 0; ni < 4; ++ni) {
            const int col = wc + ni * 8 + 2 * tig;
            const float bx = bo[col], by = bo[col + 1];
#pragma unroll
            for (int half = 0; half < 2; ++half) {
                const int row = brow + wr + mi * 16 + gid + half * 8;
                if (row >= N) continue;
                float o0 = fmaxf(C[mi][ni][half*2+0] + bx, 0.f);
                float o1 = fmaxf(C[mi][ni][half*2+1] + by, 0.f);
                if (row == 0) { o0 = 0.f; o1 = 0.f; }
                *(float2*)&out[(size_t)row * H + col] = make_float2(o0, o1);
            }
        }
}

// ---------------------------------------------------------------------------
extern "C" void kernel_launch(void* const* d_in, const int* in_sizes, int n_in,
                              void* d_out, int out_size)
{
    const float* fnode  = (const float*) d_in[0];
    const float* fmess  = (const float*) d_in[1];
    const void*  agraph = d_in[2];
    const void*  bgraph = d_in[3];
    const float* Wz     = (const float*) d_in[4];
    const float* bz     = (const float*) d_in[5];
    const float* Wr     = (const float*) d_in[6];
    const float* Ur     = (const float*) d_in[7];
    const float* bur    = (const float*) d_in[8];
    const float* Wh     = (const float*) d_in[9];
    const float* bh     = (const float*) d_in[10];
    const float* Wo     = (const float*) d_in[11];
    const float* bo     = (const float*) d_in[12];

    const int N = in_sizes[2] / 6;
    const int E = in_sizes[3] / 6;

    float *Pz, *Pr, *Ph, *hF;
    __half *fm16, *fn16, *hA16, *hB16, *q116, *q216, *Wz16, *Wr16, *Wh16, *Ur16, *Wo16;
    int *bg32, *ag32;
    cudaGetSymbolAddress((void**)&Pz,   g_Pz);
    cudaGetSymbolAddress((void**)&Pr,   g_Pr);
    cudaGetSymbolAddress((void**)&Ph,   g_Ph);
    cudaGetSymbolAddress((void**)&hF,   g_hF);
    cudaGetSymbolAddress((void**)&fm16, g_fm16);
    cudaGetSymbolAddress((void**)&fn16, g_fn16);
    cudaGetSymbolAddress((void**)&hA16, g_hA16);
    cudaGetSymbolAddress((void**)&hB16, g_hB16);
    cudaGetSymbolAddress((void**)&q116, g_q116);
    cudaGetSymbolAddress((void**)&q216, g_q216);
    cudaGetSymbolAddress((void**)&Wz16, g_Wz16);
    cudaGetSymbolAddress((void**)&Wr16, g_Wr16);
    cudaGetSymbolAddress((void**)&Wh16, g_Wh16);
    cudaGetSymbolAddress((void**)&Ur16, g_Ur16);
    cudaGetSymbolAddress((void**)&Wo16, g_Wo16);
    cudaGetSymbolAddress((void**)&bg32, g_bg32);
    cudaGetSymbolAddress((void**)&ag32, g_ag32);

    float* out_node = (float*)d_out;
    const long long need = (long long)(N + E) * H;
    const bool out_has_h = ((long long)out_size >= need);
    float* h_final32 = out_has_h ? ((float*)d_out + (size_t)N * H) : hF;

    detect_idx_kernel<<<1, 1>>>((const unsigned int*)bgraph);
    convert_idx_kernel<<<(E * 6 + 255) / 256, 256>>>(bgraph, bg32, E * 6);
    convert_idx_kernel<<<(N * 6 + 255) / 256, 256>>>(agraph, ag32, N * 6);

    // one-time fp16 conversion of inputs + weights
    f32_to_f16_kernel<<<(E * 384 / 4 + 255) / 256, 256>>>(fmess, fm16, E * 384 / 4);
    f32_to_f16_kernel<<<(N * 256 / 4 + 255) / 256, 256>>>(fnode, fn16, N * 256 / 4);
    f32_to_f16_kernel<<<(512 * H / 4 + 255) / 256, 256>>>(Wz, Wz16, 512 * H / 4);
    f32_to_f16_kernel<<<(384 * H / 4 + 255) / 256, 256>>>(Wr, Wr16, 384 * H / 4);
    f32_to_f16_kernel<<<(512 * H / 4 + 255) / 256, 256>>>(Wh, Wh16, 512 * H / 4);
    f32_to_f16_kernel<<<(H * H / 4 + 255) / 256, 256>>>(Ur, Ur16, H * H / 4);
    f32_to_f16_kernel<<<(384 * H / 4 + 255) / 256, 256>>>(Wo, Wo16, 384 * H / 4);

    const int gE128 = (E + 127) / 128;
    const int gE64  = (E + 63) / 64;
    const int gE32  = (E + 31) / 32;
    const int gN64  = (N + 63) / 64;

    // loop-invariant precompute; weight-set on blockIdx.x for L2 reuse of X
    mm3_kernel<<<dim3(3, gE128), 256>>>(fm16, 384, E, 384,
                                        Wz16, Wr16, Wh16, bz, bur, bh, Pz, Pr, Ph);

    // iteration 1 (h=0): elementwise h + fused q = h@Ur
    fused_iter1_kernel<<<gE64, 256>>>(Pz, Ph, Ur16, hA16, q116, E);

    // iteration 2: gather + dual GEMM + GRU + fused q
    fused_gru_kernel<<<gE32, 256>>>(hA16, q116, bg32, Pr, Pz, Ph,
                                    Wz16 + 384 * H, Wh16 + 384 * H, Ur16,
                                    hB16, nullptr, q216, E, 1, 0);

    // iteration 3: final h (fp32 to d_out + fp16 for node gather)
    fused_gru_kernel<<<gE32, 256>>>(hB16, q216, bg32, Pr, Pz, Ph,
                                    Wz16 + 384 * H, Wh16 + 384 * H, Ur16,
                                    hA16, h_final32, q116, E, 0, 1);

    // output head: fused gather + dual-segment GEMM
    fused_node_kernel<<<gN64, 256>>>(fn16, Wo16, hA16, ag32, bo, out_node, N);
}

// round 14
// speedup vs baseline: 1.3918x; 1.0005x over previous
#include <cuda_runtime.h>
#include <cuda_fp16.h>
#include <math.h>

#define H 128
#define E_MAX 80000
#define N_MAX 40000

// ---------------- scratch (device globals; no allocation allowed) ----------
__device__ __align__(16) float  g_Pz [E_MAX * H];
__device__ __align__(16) float  g_Pr [E_MAX * H];
__device__ __align__(16) float  g_Ph [E_MAX * H];
__device__ __align__(16) float  g_hF [E_MAX * H];       // fp32 h sink when d_out lacks h
__device__ __align__(16) __half g_fm16[E_MAX * 384];
__device__ __align__(16) __half g_fn16[N_MAX * 256];
__device__ __align__(16) __half g_hA16[E_MAX * H];
__device__ __align__(16) __half g_hB16[E_MAX * H];
__device__ __align__(16) __half g_q116[E_MAX * H];
__device__ __align__(16) __half g_q216[E_MAX * H];
__device__ __align__(16) __half g_Wz16[512 * H];
__device__ __align__(16) __half g_Wr16[384 * H];
__device__ __align__(16) __half g_Wh16[512 * H];
__device__ __align__(16) __half g_Ur16[H * H];
__device__ __align__(16) __half g_Wo16[384 * H];
__device__ int g_bg32[E_MAX * 6];
__device__ int g_ag32[N_MAX * 6];
__device__ int g_idx_is64;

__device__ __forceinline__ float sigmoidf_(float x) { return 1.0f / (1.0f + expf(-x)); }
__device__ __forceinline__ unsigned pk(float a, float b) {
    __half2 h = __floats2half2_rn(a, b);
    return *reinterpret_cast<unsigned*>(&h);
}
__device__ __forceinline__ float2 up(unsigned u) {
    return __half22float2(*reinterpret_cast<__half2*>(&u));
}

#define MMA_F16(C, A0,A1,A2,A3, B0,B1) \
    asm volatile("mma.sync.aligned.m16n8k16.row.col.f32.f16.f16.f32 " \
        "{%0,%1,%2,%3},{%4,%5,%6,%7},{%8,%9},{%0,%1,%2,%3};" \
        : "+f"((C)[0]), "+f"((C)[1]), "+f"((C)[2]), "+f"((C)[3]) \
        : "r"(A0), "r"(A1), "r"(A2), "r"(A3), "r"(B0), "r"(B1))

#define LDSM_X4(R0,R1,R2,R3,ADDR) \
    asm volatile("ldmatrix.sync.aligned.m8n8.x4.shared.b16 {%0,%1,%2,%3}, [%4];" \
        : "=r"(R0), "=r"(R1), "=r"(R2), "=r"(R3) : "r"(ADDR))

#define LDSM_X4_T(R0,R1,R2,R3,ADDR) \
    asm volatile("ldmatrix.sync.aligned.m8n8.x4.trans.shared.b16 {%0,%1,%2,%3}, [%4];" \
        : "=r"(R0), "=r"(R1), "=r"(R2), "=r"(R3) : "r"(ADDR))

#define WB_BYTES 4352   // 16*136*2

// ---------------------------------------------------------------------------
// prep kernels
// ---------------------------------------------------------------------------
__global__ void detect_idx_kernel(const unsigned int* __restrict__ w)
{
    g_idx_is64 = (w[1] == 0u && w[3] == 0u && w[5] == 0u && w[7] == 0u) ? 1 : 0;
}
__global__ void convert_idx_kernel(const void* __restrict__ src, int* __restrict__ dst, int n)
{
    int i = blockIdx.x * blockDim.x + threadIdx.x;
    if (i >= n) return;
    if (g_idx_is64) dst[i] = (int)((const long long*)src)[i];
    else            dst[i] = ((const int*)src)[i];
}
__global__ void f32_to_f16_kernel(const float* __restrict__ src, __half* __restrict__ dst, int n4)
{
    int i = blockIdx.x * blockDim.x + threadIdx.x;
    if (i >= n4) return;
    const float4 v = ((const float4*)src)[i];
    uint2 o; o.x = pk(v.x, v.y); o.y = pk(v.z, v.w);
    ((uint2*)dst)[i] = o;
}

// ---------------------------------------------------------------------------
// fp16 GEMM helper, double-buffered W staging (1 sync per k-chunk).
// A resident in smem halves [rows][136] (272B stride); W fp16 gmem [128][128].
// ---------------------------------------------------------------------------
template<int NT>
__device__ __forceinline__ void gemm_smemA_f16(
    unsigned AsB, const __half* __restrict__ W,
    __half (*Wb)[16][136], unsigned WbB,
    float (&C)[2][NT][4],
    int wr, int wc, int lane, int tid)
{
    const int aRowOff = (wr + (lane & 15)) * 272 + ((lane >> 4) * 8) * 2;
    const int bAddr0  = ((lane & 7) + ((lane >> 3) & 1) * 8) * 272
                      + (wc + (lane >> 4) * 8) * 2;
    const int wrow = tid >> 4, wcb = (tid & 15) * 8;

    *(uint4*)&Wb[0][wrow][wcb] = *(const uint4*)&W[(size_t)wrow * H + wcb];
    __syncthreads();

#pragma unroll
    for (int k0 = 0; k0 < 128; k0 += 16) {
        const int buf = (k0 >> 4) & 1;
        if (k0 + 16 < 128)
            *(uint4*)&Wb[buf ^ 1][wrow][wcb] =
                *(const uint4*)&W[(size_t)(k0 + 16 + wrow) * H + wcb];

        unsigned a[2][4];
#pragma unroll
        for (int mi = 0; mi < 2; ++mi)
            LDSM_X4(a[mi][0], a[mi][1], a[mi][2], a[mi][3],
                    AsB + aRowOff + mi * 16 * 272 + k0 * 2);
#pragma unroll
        for (int pr = 0; pr < NT / 2; ++pr) {
            unsigned b0, b1, b2, b3;
            LDSM_X4_T(b0, b1, b2, b3, WbB + buf * WB_BYTES + bAddr0 + pr * 32);
            MMA_F16(C[0][2*pr],   a[0][0], a[0][1], a[0][2], a[0][3], b0, b1);
            MMA_F16(C[0][2*pr+1], a[0][0], a[0][1], a[0][2], a[0][3], b2, b3);
            MMA_F16(C[1][2*pr],   a[1][0], a[1][1], a[1][2], a[1][3], b0, b1);
            MMA_F16(C[1][2*pr+1], a[1][0], a[1][1], a[1][2], a[1][3], b2, b3);
        }
        __syncthreads();
    }
}

// ---------------------------------------------------------------------------
// mm3 (unchanged proven config): X,W fp16; BM=128; fully double-buffered;
// grid (3, rowTiles) for X L2 reuse.
// ---------------------------------------------------------------------------
__global__ void __launch_bounds__(256)
mm3_kernel(const __half* __restrict__ X, int ldx, int M, int K,
           const __half* __restrict__ W0, const __half* __restrict__ W1, const __half* __restrict__ W2,
           const float* __restrict__ b0, const float* __restrict__ b1, const float* __restrict__ b2,
           float* __restrict__ o0, float* __restrict__ o1, float* __restrict__ o2)
{
    __shared__ __align__(16) __half Xs[2][128][24];
    __shared__ __align__(16) __half Ws[2][16][136];

    const __half* W  = (blockIdx.x == 0) ? W0 : (blockIdx.x == 1) ? W1 : W2;
    const float* bia = (blockIdx.x == 0) ? b0 : (blockIdx.x == 1) ? b1 : b2;
    float*       out = (blockIdx.x == 0) ? o0 : (blockIdx.x == 1) ? o1 : o2;

    const int tid = threadIdx.x, warp = tid >> 5, lane = tid & 31;
    const int gid = lane >> 2, tig = lane & 3;
    const int wr = (warp >> 1) * 32, wc = (warp & 1) * 64;
    const int brow = blockIdx.y * 128;

    const int xrow = tid >> 1, xcb = (tid & 1) * 8;
    const int wrow = tid >> 4, wcb = (tid & 15) * 8;
    const int xgr  = brow + xrow;

    const unsigned xs0 = (unsigned)__cvta_generic_to_shared(&Xs[0][0][0]);
    const unsigned ws0 = (unsigned)__cvta_generic_to_shared(&Ws[0][0][0]);
    const int aRowOff = (wr + (lane & 15)) * 48 + ((lane >> 4) * 8) * 2;
    const int bAddr0  = ((lane & 7) + ((lane >> 3) & 1) * 8) * 272
                      + (wc + (lane >> 4) * 8) * 2;

    float C[2][8][4];
#pragma unroll
    for (int i = 0; i < 2; ++i)
#pragma unroll
        for (int j = 0; j < 8; ++j)
#pragma unroll
            for (int k = 0; k < 4; ++k) C[i][j][k] = 0.f;

    uint4 xw = make_uint4(0,0,0,0), ww;
    if (xgr < M) xw = *(const uint4*)&X[(size_t)xgr * ldx + xcb];
    ww = *(const uint4*)&W[(size_t)wrow * H + wcb];
    *(uint4*)&Xs[0][xrow][xcb] = xw;
    *(uint4*)&Ws[0][wrow][wcb] = ww;
    __syncthreads();

    const int nk = K >> 4;
    for (int it = 0; it < nk; ++it) {
        const int buf = it & 1;
        if (it + 1 < nk) {
            const int k0 = (it + 1) << 4;
            xw = make_uint4(0,0,0,0);
            if (xgr < M) xw = *(const uint4*)&X[(size_t)xgr * ldx + k0 + xcb];
            ww = *(const uint4*)&W[(size_t)(k0 + wrow) * H + wcb];
        }
        {
            const unsigned xb = xs0 + buf * 6144;
            const unsigned wb = ws0 + buf * WB_BYTES;
            unsigned a[2][4];
#pragma unroll
            for (int mi = 0; mi < 2; ++mi)
                LDSM_X4(a[mi][0], a[mi][1], a[mi][2], a[mi][3],
                        xb + aRowOff + mi * 16 * 48);
#pragma unroll
            for (int pr = 0; pr < 4; ++pr) {
                unsigned bb0, bb1, bb2, bb3;
                LDSM_X4_T(bb0, bb1, bb2, bb3, wb + bAddr0 + pr * 32);
                MMA_F16(C[0][2*pr],   a[0][0], a[0][1], a[0][2], a[0][3], bb0, bb1);
                MMA_F16(C[0][2*pr+1], a[0][0], a[0][1], a[0][2], a[0][3], bb2, bb3);
                MMA_F16(C[1][2*pr],   a[1][0], a[1][1], a[1][2], a[1][3], bb0, bb1);
                MMA_F16(C[1][2*pr+1], a[1][0], a[1][1], a[1][2], a[1][3], bb2, bb3);
            }
        }
        if (it + 1 < nk) {
            const int nb = buf ^ 1;
            *(uint4*)&Xs[nb][xrow][xcb] = xw;
            *(uint4*)&Ws[nb][wrow][wcb] = ww;
        }
        __syncthreads();
    }

#pragma unroll
    for (int mi = 0; mi < 2; ++mi)
#pragma unroll
        for (int ni = 0; ni < 8; ++ni) {
            const int col = wc + ni * 8 + 2 * tig;
            const float bx = bia ? bia[col] : 0.f;
            const float by = bia ? bia[col + 1] : 0.f;
            const int r0 = brow + wr + mi * 16 + gid;
            const int r1 = r0 + 8;
            if (r0 < M) *(float2*)&out[(size_t)r0 * H + col] =
                make_float2(C[mi][ni][0] + bx, C[mi][ni][1] + by);
            if (r1 < M) *(float2*)&out[(size_t)r1 * H + col] =
                make_float2(C[mi][ni][2] + bx, C[mi][ni][3] + by);
        }
}

// ---------------------------------------------------------------------------
// fused_iter1: h = sigmoid(Pz)*tanh(Ph) -> fp16 global + smem; q16 = h @ Ur.
// BM=64, warps 2x4 (NT=4); double-buffered Wb.
// ---------------------------------------------------------------------------
__global__ void __launch_bounds__(256)
fused_iter1_kernel(const float* __restrict__ Pz, const float* __restrict__ Ph,
                   const __half* __restrict__ Ur,
                   __half* __restrict__ h_out, __half* __restrict__ q_out, int E)
{
    __shared__ __align__(16) __half As[64][136];
    __shared__ __align__(16) __half Wb[2][16][136];

    const int tid = threadIdx.x, lane = tid & 31, ty = tid >> 5;
    const int gid = lane >> 2, tig = lane & 3;
    const int wr = (ty >> 2) * 32, wc = (ty & 3) * 32;
    const int brow = blockIdx.x * 64;
    const int c4 = lane * 4;

    const unsigned AsB = (unsigned)__cvta_generic_to_shared(&As[0][0]);
    const unsigned WbB = (unsigned)__cvta_generic_to_shared(&Wb[0][0][0]);

#pragma unroll
    for (int pass = 0; pass < 8; ++pass) {
        const int er = pass * 8 + ty;
        const int e  = brow + er;
        float4 v = make_float4(0.f,0.f,0.f,0.f);
        uint2 hv;
        if (e < E) {
            const float4 pz = *(const float4*)&Pz[(size_t)e*H + c4];
            const float4 ph = *(const float4*)&Ph[(size_t)e*H + c4];
            v.x = sigmoidf_(pz.x) * tanhf(ph.x);
            v.y = sigmoidf_(pz.y) * tanhf(ph.y);
            v.z = sigmoidf_(pz.z) * tanhf(ph.z);
            v.w = sigmoidf_(pz.w) * tanhf(ph.w);
            if (e == 0) v = make_float4(0.f,0.f,0.f,0.f);
            hv.x = pk(v.x, v.y); hv.y = pk(v.z, v.w);
            *(uint2*)&h_out[(size_t)e*H + c4] = hv;
        } else { hv.x = 0u; hv.y = 0u; }
        *(uint2*)&As[er][c4] = hv;
    }
    __syncthreads();

    float C[2][4][4];
#pragma unroll
    for (int i = 0; i < 2; ++i)
#pragma unroll
        for (int j = 0; j < 4; ++j)
#pragma unroll
            for (int k = 0; k < 4; ++k) C[i][j][k] = 0.f;
    gemm_smemA_f16<4>(AsB, Ur, Wb, WbB, C, wr, wc, lane, tid);

#pragma unroll
    for (int mi = 0; mi < 2; ++mi)
#pragma unroll
        for (int ni = 0; ni < 4; ++ni) {
            const int col = wc + ni * 8 + 2 * tig;
            const int r0 = brow + wr + mi * 16 + gid;
            const int r1 = r0 + 8;
            if (r0 < E) *(unsigned*)&q_out[(size_t)r0 * H + col] =
                pk(C[mi][ni][0], C[mi][ni][1]);
            if (r1 < E) *(unsigned*)&q_out[(size_t)r1 * H + col] =
                pk(C[mi][ni][2], C[mi][ni][3]);
        }
}

// ---------------------------------------------------------------------------
// fused_gru: BM=32, warps 1x8 (NT=2).  Merged z/h GEMM pass (one k-loop,
// both weight chunks double-buffered) -> 8 syncs instead of 32; q pass
// double-buffered (8 syncs instead of 16).
// ---------------------------------------------------------------------------
__global__ void __launch_bounds__(256)
fused_gru_kernel(const __half* __restrict__ h_in, const __half* __restrict__ q_in,
                 const int* __restrict__ bg,
                 const float* __restrict__ Pr, const float* __restrict__ Pz,
                 const float* __restrict__ Ph,
                 const __half* __restrict__ Wz2, const __half* __restrict__ Wh2,
                 const __half* __restrict__ Ur,
                 __half* __restrict__ h16_out, float* __restrict__ h32_out,
                 __half* __restrict__ q_out,
                 int E, int do_q, int do_f32)
{
    __shared__ __align__(16) __half SHs[32][136];
    __shared__ __align__(16) __half SGs[32][136];
    __shared__ __align__(16) __half WbZ[2][16][136];
    __shared__ __align__(16) __half WbH[2][16][136];

    const int tid = threadIdx.x, lane = tid & 31, ty = tid >> 5;
    const int gid = lane >> 2, tig = lane & 3;
    const int wc = ty * 16;
    const int brow = blockIdx.x * 32;
    const int c4 = lane * 4;
    const int wrow = tid >> 4, wcb = (tid & 15) * 8;

    const unsigned SHB  = (unsigned)__cvta_generic_to_shared(&SHs[0][0]);
    const unsigned SGB  = (unsigned)__cvta_generic_to_shared(&SGs[0][0]);
    const unsigned WbZB = (unsigned)__cvta_generic_to_shared(&WbZ[0][0][0]);
    const unsigned WbHB = (unsigned)__cvta_generic_to_shared(&WbH[0][0][0]);

    // gather phase: 32 edges, 6 neighbors each
#pragma unroll
    for (int pass = 0; pass < 4; ++pass) {
        const int er = pass * 8 + ty;
        const int e  = brow + er;
        float4 sh = make_float4(0.f,0.f,0.f,0.f);
        float4 sg = make_float4(0.f,0.f,0.f,0.f);
        if (e < E) {
            const float4 pr = *(const float4*)&Pr[(size_t)e*H + c4];
#pragma unroll
            for (int j = 0; j < 6; ++j) {
                const int idx = __ldg(&bg[e * 6 + j]);
                const uint2 hv = *(const uint2*)&h_in[(size_t)idx*H + c4];
                const uint2 qv = *(const uint2*)&q_in[(size_t)idx*H + c4];
                const float2 h01 = up(hv.x), h23 = up(hv.y);
                const float2 q01 = up(qv.x), q23 = up(qv.y);
                sh.x += h01.x; sh.y += h01.y; sh.z += h23.x; sh.w += h23.y;
                sg.x += h01.x * sigmoidf_(pr.x + q01.x);
                sg.y += h01.y * sigmoidf_(pr.y + q01.y);
                sg.z += h23.x * sigmoidf_(pr.z + q23.x);
                sg.w += h23.y * sigmoidf_(pr.w + q23.y);
            }
        }
        uint2 a; a.x = pk(sh.x, sh.y); a.y = pk(sh.z, sh.w);
        *(uint2*)&SHs[er][c4] = a;
        uint2 b; b.x = pk(sg.x, sg.y); b.y = pk(sg.z, sg.w);
        *(uint2*)&SGs[er][c4] = b;
    }

    // ---- merged dual GEMM: Cz = SHs @ Wz2, Ch = SGs @ Wh2 (one k-loop) ----
    float Cz[2][2][4], Ch[2][2][4];
#pragma unroll
    for (int i = 0; i < 2; ++i)
#pragma unroll
        for (int j = 0; j < 2; ++j)
#pragma unroll
            for (int k = 0; k < 4; ++k) { Cz[i][j][k] = 0.f; Ch[i][j][k] = 0.f; }

    const int aRowOff = (lane & 15) * 272 + ((lane >> 4) * 8) * 2;
    const int bAddr0  = ((lane & 7) + ((lane >> 3) & 1) * 8) * 272
                      + (wc + (lane >> 4) * 8) * 2;

    *(uint4*)&WbZ[0][wrow][wcb] = *(const uint4*)&Wz2[(size_t)wrow * H + wcb];
    *(uint4*)&WbH[0][wrow][wcb] = *(const uint4*)&Wh2[(size_t)wrow * H + wcb];
    __syncthreads();

#pragma unroll
    for (int k0 = 0; k0 < 128; k0 += 16) {
        const int buf = (k0 >> 4) & 1;
        if (k0 + 16 < 128) {
            *(uint4*)&WbZ[buf ^ 1][wrow][wcb] =
                *(const uint4*)&Wz2[(size_t)(k0 + 16 + wrow) * H + wcb];
            *(uint4*)&WbH[buf ^ 1][wrow][wcb] =
                *(const uint4*)&Wh2[(size_t)(k0 + 16 + wrow) * H + wcb];
        }
        unsigned az[2][4], ah[2][4];
#pragma unroll
        for (int mi = 0; mi < 2; ++mi) {
            LDSM_X4(az[mi][0], az[mi][1], az[mi][2], az[mi][3],
                    SHB + aRowOff + mi * 16 * 272 + k0 * 2);
            LDSM_X4(ah[mi][0], ah[mi][1], ah[mi][2], ah[mi][3],
                    SGB + aRowOff + mi * 16 * 272 + k0 * 2);
        }
        unsigned bz0, bz1, bz2, bz3, bh0, bh1, bh2, bh3;
        LDSM_X4_T(bz0, bz1, bz2, bz3, WbZB + buf * WB_BYTES + bAddr0);
        LDSM_X4_T(bh0, bh1, bh2, bh3, WbHB + buf * WB_BYTES + bAddr0);
        MMA_F16(Cz[0][0], az[0][0], az[0][1], az[0][2], az[0][3], bz0, bz1);
        MMA_F16(Cz[0][1], az[0][0], az[0][1], az[0][2], az[0][3], bz2, bz3);
        MMA_F16(Cz[1][0], az[1][0], az[1][1], az[1][2], az[1][3], bz0, bz1);
        MMA_F16(Cz[1][1], az[1][0], az[1][1], az[1][2], az[1][3], bz2, bz3);
        MMA_F16(Ch[0][0], ah[0][0], ah[0][1], ah[0][2], ah[0][3], bh0, bh1);
        MMA_F16(Ch[0][1], ah[0][0], ah[0][1], ah[0][2], ah[0][3], bh2, bh3);
        MMA_F16(Ch[1][0], ah[1][0], ah[1][1], ah[1][2], ah[1][3], bh0, bh1);
        MMA_F16(Ch[1][1], ah[1][0], ah[1][1], ah[1][2], ah[1][3], bh2, bh3);
        __syncthreads();
    }

    // GRU epilogue; write h16 (+h32 opt), refill SHs with h_new for q-GEMM
#pragma unroll
    for (int mi = 0; mi < 2; ++mi)
#pragma unroll
        for (int ni = 0; ni < 2; ++ni) {
            const int col = wc + ni * 8 + 2 * tig;
#pragma unroll
            for (int half = 0; half < 2; ++half) {
                const int lr  = mi * 16 + gid + half * 8;
                const int row = brow + lr;
                if (row >= E) continue;
                const size_t base = (size_t)row * H + col;
                const float2 pz = *(const float2*)&Pz[base];
                const float2 ph = *(const float2*)&Ph[base];
                const float sh0 = __half2float(SHs[lr][col]);
                const float sh1 = __half2float(SHs[lr][col + 1]);
                const float z0 = sigmoidf_(Cz[mi][ni][half*2+0] + pz.x);
                const float z1 = sigmoidf_(Cz[mi][ni][half*2+1] + pz.y);
                const float p0 = tanhf(Ch[mi][ni][half*2+0] + ph.x);
                const float p1 = tanhf(Ch[mi][ni][half*2+1] + ph.y);
                float o0 = (1.f - z0) * sh0 + z0 * p0;
                float o1 = (1.f - z1) * sh1 + z1 * p1;
                if (row == 0) { o0 = 0.f; o1 = 0.f; }
                const unsigned po = pk(o0, o1);
                *(unsigned*)&h16_out[base] = po;
                if (do_f32) *(float2*)&h32_out[base] = make_float2(o0, o1);
                *(unsigned*)&SHs[lr][col] = po;
            }
        }
    if (!do_q) return;
    __syncthreads();

    float Cq[2][2][4];
#pragma unroll
    for (int i = 0; i < 2; ++i)
#pragma unroll
        for (int j = 0; j < 2; ++j)
#pragma unroll
            for (int k = 0; k < 4; ++k) Cq[i][j][k] = 0.f;
    gemm_smemA_f16<2>(SHB, Ur, WbZ, WbZB, Cq, 0, wc, lane, tid);

#pragma unroll
    for (int mi = 0; mi < 2; ++mi)
#pragma unroll
        for (int ni = 0; ni < 2; ++ni) {
            const int col = wc + ni * 8 + 2 * tig;
            const int r0 = brow + mi * 16 + gid;
            const int r1 = r0 + 8;
            if (r0 < E) *(unsigned*)&q_out[(size_t)r0 * H + col] =
                pk(Cq[mi][ni][0], Cq[mi][ni][1]);
            if (r1 < E) *(unsigned*)&q_out[(size_t)r1 * H + col] =
                pk(Cq[mi][ni][2], Cq[mi][ni][3]);
        }
}

// ---------------------------------------------------------------------------
// fused_node: BM=64, warps 2x4 (NT=4).  Phase A double-buffered (A chunk in
// As cols 0/16 alternating, W in Wb[2]) -> 1 sync per chunk.
// ---------------------------------------------------------------------------
__global__ void __launch_bounds__(256)
fused_node_kernel(const __half* __restrict__ fnode, const __half* __restrict__ Wo,
                  const __half* __restrict__ h, const int* __restrict__ ag,
                  const float* __restrict__ bo, float* __restrict__ out, int N)
{
    __shared__ __align__(16) __half As[64][136];
    __shared__ __align__(16) __half Wb[2][16][136];

    const int tid = threadIdx.x, lane = tid & 31, ty = tid >> 5;
    const int gid = lane >> 2, tig = lane & 3;
    const int wr = (ty >> 2) * 32, wc = (ty & 3) * 32;
    const int brow = blockIdx.x * 64;
    const int c4 = lane * 4;

    const unsigned AsB = (unsigned)__cvta_generic_to_shared(&As[0][0]);
    const unsigned WbB = (unsigned)__cvta_generic_to_shared(&Wb[0][0][0]);
    const int aRowOff = (wr + (lane & 15)) * 272 + ((lane >> 4) * 8) * 2;
    const int bAddr0  = ((lane & 7) + ((lane >> 3) & 1) * 8) * 272
                      + (wc + (lane >> 4) * 8) * 2;
    const int wrow = tid >> 4, wcb = (tid & 15) * 8;
    const int arow = tid >> 2, acb = (tid & 3) * 4;

    float C[2][4][4];
#pragma unroll
    for (int i = 0; i < 2; ++i)
#pragma unroll
        for (int j = 0; j < 4; ++j)
#pragma unroll
            for (int k = 0; k < 4; ++k) C[i][j][k] = 0.f;

    // phase A: fnode @ Wo[0:256], double-buffered chunks
    {
        uint2 hv = make_uint2(0u, 0u);
        if (brow + arow < N) hv = *(const uint2*)&fnode[(size_t)(brow + arow) * 256 + acb];
        *(uint2*)&As[arow][acb] = hv;
        *(uint4*)&Wb[0][wrow][wcb] = *(const uint4*)&Wo[(size_t)wrow * H + wcb];
    }
    __syncthreads();

    for (int k0 = 0; k0 < 256; k0 += 16) {
        const int buf = (k0 >> 4) & 1;
        if (k0 + 16 < 256) {
            uint2 hv = make_uint2(0u, 0u);
            if (brow + arow < N)
                hv = *(const uint2*)&fnode[(size_t)(brow + arow) * 256 + k0 + 16 + acb];
            *(uint2*)&As[arow][(buf ^ 1) * 16 + acb] = hv;
            *(uint4*)&Wb[buf ^ 1][wrow][wcb] =
                *(const uint4*)&Wo[(size_t)(k0 + 16 + wrow) * H + wcb];
        }
        unsigned a[2][4];
#pragma unroll
        for (int mi = 0; mi < 2; ++mi)
            LDSM_X4(a[mi][0], a[mi][1], a[mi][2], a[mi][3],
                    AsB + aRowOff + mi * 16 * 272 + buf * 32);
#pragma unroll
        for (int pr = 0; pr < 2; ++pr) {
            unsigned bb0, bb1, bb2, bb3;
            LDSM_X4_T(bb0, bb1, bb2, bb3, WbB + buf * WB_BYTES + bAddr0 + pr * 32);
            MMA_F16(C[0][2*pr],   a[0][0], a[0][1], a[0][2], a[0][3], bb0, bb1);
            MMA_F16(C[0][2*pr+1], a[0][0], a[0][1], a[0][2], a[0][3], bb2, bb3);
            MMA_F16(C[1][2*pr],   a[1][0], a[1][1], a[1][2], a[1][3], bb0, bb1);
            MMA_F16(C[1][2*pr+1], a[1][0], a[1][1], a[1][2], a[1][3], bb2, bb3);
        }
        __syncthreads();
    }

    // phase B: gather nei into As (full width)
#pragma unroll
    for (int pass = 0; pass < 8; ++pass) {
        const int nr = pass * 8 + ty;
        const int n  = brow + nr;
        float4 s = make_float4(0.f,0.f,0.f,0.f);
        if (n < N) {
#pragma unroll
            for (int j = 0; j < 6; ++j) {
                const int idx = __ldg(&ag[n * 6 + j]);
                const uint2 hv = *(const uint2*)&h[(size_t)idx*H + c4];
                const float2 h01 = up(hv.x), h23 = up(hv.y);
                s.x += h01.x; s.y += h01.y; s.z += h23.x; s.w += h23.y;
            }
        }
        uint2 hv; hv.x = pk(s.x, s.y); hv.y = pk(s.z, s.w);
        *(uint2*)&As[nr][c4] = hv;
    }
    __syncthreads();

    gemm_smemA_f16<4>(AsB, Wo + 256 * H, Wb, WbB, C, wr, wc, lane, tid);

#pragma unroll
    for (int mi = 0; mi < 2; ++mi)
#pragma unroll
        for (int ni = 0; ni < 4; ++ni) {
            const int col = wc + ni * 8 + 2 * tig;
            const float bx = bo[col], by = bo[col + 1];
#pragma unroll
            for (int half = 0; half < 2; ++half) {
                const int row = brow + wr + mi * 16 + gid + half * 8;
                if (row >= N) continue;
                float o0 = fmaxf(C[mi][ni][half*2+0] + bx, 0.f);
                float o1 = fmaxf(C[mi][ni][half*2+1] + by, 0.f);
                if (row == 0) { o0 = 0.f; o1 = 0.f; }
                *(float2*)&out[(size_t)row * H + col] = make_float2(o0, o1);
            }
        }
}

// ---------------------------------------------------------------------------
extern "C" void kernel_launch(void* const* d_in, const int* in_sizes, int n_in,
                              void* d_out, int out_size)
{
    const float* fnode  = (const float*) d_in[0];
    const float* fmess  = (const float*) d_in[1];
    const void*  agraph = d_in[2];
    const void*  bgraph = d_in[3];
    const float* Wz     = (const float*) d_in[4];
    const float* bz     = (const float*) d_in[5];
    const float* Wr     = (const float*) d_in[6];
    const float* Ur     = (const float*) d_in[7];
    const float* bur    = (const float*) d_in[8];
    const float* Wh     = (const float*) d_in[9];
    const float* bh     = (const float*) d_in[10];
    const float* Wo     = (const float*) d_in[11];
    const float* bo     = (const float*) d_in[12];

    const int N = in_sizes[2] / 6;
    const int E = in_sizes[3] / 6;

    float *Pz, *Pr, *Ph, *hF;
    __half *fm16, *fn16, *hA16, *hB16, *q116, *q216, *Wz16, *Wr16, *Wh16, *Ur16, *Wo16;
    int *bg32, *ag32;
    cudaGetSymbolAddress((void**)&Pz,   g_Pz);
    cudaGetSymbolAddress((void**)&Pr,   g_Pr);
    cudaGetSymbolAddress((void**)&Ph,   g_Ph);
    cudaGetSymbolAddress((void**)&hF,   g_hF);
    cudaGetSymbolAddress((void**)&fm16, g_fm16);
    cudaGetSymbolAddress((void**)&fn16, g_fn16);
    cudaGetSymbolAddress((void**)&hA16, g_hA16);
    cudaGetSymbolAddress((void**)&hB16, g_hB16);
    cudaGetSymbolAddress((void**)&q116, g_q116);
    cudaGetSymbolAddress((void**)&q216, g_q216);
    cudaGetSymbolAddress((void**)&Wz16, g_Wz16);
    cudaGetSymbolAddress((void**)&Wr16, g_Wr16);
    cudaGetSymbolAddress((void**)&Wh16, g_Wh16);
    cudaGetSymbolAddress((void**)&Ur16, g_Ur16);
    cudaGetSymbolAddress((void**)&Wo16, g_Wo16);
    cudaGetSymbolAddress((void**)&bg32, g_bg32);
    cudaGetSymbolAddress((void**)&ag32, g_ag32);

    float* out_node = (float*)d_out;
    const long long need = (long long)(N + E) * H;
    const bool out_has_h = ((long long)out_size >= need);
    float* h_final32 = out_has_h ? ((float*)d_out + (size_t)N * H) : hF;

    detect_idx_kernel<<<1, 1>>>((const unsigned int*)bgraph);
    convert_idx_kernel<<<(E * 6 + 255) / 256, 256>>>(bgraph, bg32, E * 6);
    convert_idx_kernel<<<(N * 6 + 255) / 256, 256>>>(agraph, ag32, N * 6);

    // one-time fp16 conversion of inputs + weights
    f32_to_f16_kernel<<<(E * 384 / 4 + 255) / 256, 256>>>(fmess, fm16, E * 384 / 4);
    f32_to_f16_kernel<<<(N * 256 / 4 + 255) / 256, 256>>>(fnode, fn16, N * 256 / 4);
    f32_to_f16_kernel<<<(512 * H / 4 + 255) / 256, 256>>>(Wz, Wz16, 512 * H / 4);
    f32_to_f16_kernel<<<(384 * H / 4 + 255) / 256, 256>>>(Wr, Wr16, 384 * H / 4);
    f32_to_f16_kernel<<<(512 * H / 4 + 255) / 256, 256>>>(Wh, Wh16, 512 * H / 4);
    f32_to_f16_kernel<<<(H * H / 4 + 255) / 256, 256>>>(Ur, Ur16, H * H / 4);
    f32_to_f16_kernel<<<(384 * H / 4 + 255) / 256, 256>>>(Wo, Wo16, 384 * H / 4);

    const int gE128 = (E + 127) / 128;
    const int gE64  = (E + 63) / 64;
    const int gE32  = (E + 31) / 32;
    const int gN64  = (N + 63) / 64;

    // loop-invariant precompute; weight-set on blockIdx.x for L2 reuse of X
    mm3_kernel<<<dim3(3, gE128), 256>>>(fm16, 384, E, 384,
                                        Wz16, Wr16, Wh16, bz, bur, bh, Pz, Pr, Ph);

    // iteration 1 (h=0): elementwise h + fused q = h@Ur
    fused_iter1_kernel<<<gE64, 256>>>(Pz, Ph, Ur16, hA16, q116, E);

    // iteration 2: gather + merged dual GEMM + GRU + fused q
    fused_gru_kernel<<<gE32, 256>>>(hA16, q116, bg32, Pr, Pz, Ph,
                                    Wz16 + 384 * H, Wh16 + 384 * H, Ur16,
                                    hB16, nullptr, q216, E, 1, 0);

    // iteration 3: final h (fp32 to d_out + fp16 for node gather)
    fused_gru_kernel<<<gE32, 256>>>(hB16, q216, bg32, Pr, Pz, Ph,
                                    Wz16 + 384 * H, Wh16 + 384 * H, Ur16,
                                    hA16, h_final32, q116, E, 0, 1);

    // output head: fused gather + dual-segment GEMM
    fused_node_kernel<<<gN64, 256>>>(fn16, Wo16, hA16, ag32, bo, out_node, N);
}